// round 1
// baseline (speedup 1.0000x reference)
#include <cuda_runtime.h>
#include <math.h>

#define BB   8
#define SS   1024
#define DD   1024
#define HH   16
#define DKK  64
#define CFF  256
#define MT   (BB*SS)          // 8192 rows
#define OUT_ELEMS  (MT*DD)    // 8388608
#define SCALE_F 512.0f

// ---------------- scratch (static device memory; no allocs allowed) -------------
__device__ float d_qbuf[MT*DD];
__device__ float d_kbuf[MT*DD];
__device__ float d_vbuf[MT*DD];
__device__ float d_ctxbuf[MT*DD];
__device__ float d_caddbuf[3*BB*DD];

// ---------------- small c-branch: y = LN(c @ Wc + b) --------------------------
__global__ void cproj_kernel(const float* __restrict__ c,
    const float* __restrict__ Wcq, const float* __restrict__ bcq,
    const float* __restrict__ Wck, const float* __restrict__ bck,
    const float* __restrict__ Wcv, const float* __restrict__ bcv,
    const float* __restrict__ gqc, const float* __restrict__ beqc,
    const float* __restrict__ gkc, const float* __restrict__ bekc,
    const float* __restrict__ gvc, const float* __restrict__ bevc,
    float* __restrict__ cadd)
{
    int p = blockIdx.x;   // 0=q,1=k,2=v
    int b = blockIdx.y;
    int t = threadIdx.x;  // 256
    const float* W  = (p==0)?Wcq:((p==1)?Wck:Wcv);
    const float* bi = (p==0)?bcq:((p==1)?bck:bcv);
    const float* g  = (p==0)?gqc:((p==1)?gkc:gvc);
    const float* be = (p==0)?beqc:((p==1)?bekc:bevc);

    __shared__ float sc[CFF];
    __shared__ float red[256];
    sc[t] = c[b*CFF + t];
    __syncthreads();

    float y[4];
#pragma unroll
    for (int jj=0;jj<4;jj++){
        int j = jj*256 + t;
        float acc = bi[j];
        for (int i=0;i<CFF;i++) acc += sc[i]*W[(size_t)i*DD + j];
        y[jj]=acc;
    }
    float s = (y[0]+y[1])+(y[2]+y[3]);
    red[t]=s; __syncthreads();
    for (int st=128;st>0;st>>=1){ if(t<st) red[t]+=red[t+st]; __syncthreads(); }
    float mu = red[0]*(1.0f/DD);
    __syncthreads();
    float vv=0.f;
#pragma unroll
    for (int jj=0;jj<4;jj++){ float d0=y[jj]-mu; vv += d0*d0; }
    red[t]=vv; __syncthreads();
    for (int st=128;st>0;st>>=1){ if(t<st) red[t]+=red[t+st]; __syncthreads(); }
    float var = red[0]*(1.0f/DD);
    float rs = 1.0f/sqrtf(var + 1e-5f);
#pragma unroll
    for (int jj=0;jj<4;jj++){
        int j = jj*256 + t;
        cadd[(size_t)(p*BB + b)*DD + j] = (y[jj]-mu)*rs*g[j] + be[j];
    }
}

// ---------------- fp32 SGEMM: C[M=8192][1024] = A @ Bw + bias -----------------
// BM=BN=128, BK=16, 256 threads, 8x8 microtile
__global__ void __launch_bounds__(256) sgemm_bias(
    const float* __restrict__ A, const float* __restrict__ Bw,
    const float* __restrict__ bias, float* __restrict__ C)
{
    __shared__ float As[16][128];
    __shared__ float Bs[16][128];
    int t  = threadIdx.x;
    int m0 = blockIdx.y*128, n0 = blockIdx.x*128;
    int ty = t>>4, tx = t&15;

    float acc[8][8];
#pragma unroll
    for (int i=0;i<8;i++)
#pragma unroll
        for (int j=0;j<8;j++) acc[i][j]=0.f;

    int arow = t>>2;            // 0..63 (second load = +64)
    int akq  = (t&3)*4;         // 0,4,8,12
    int kr   = t>>5;            // 0..7 (second load = +8)
    int nc   = (t&31)*4;        // 0..124

    for (int k0=0;k0<DD;k0+=16){
        float4 a0 = *(const float4*)(A  + (size_t)(m0+arow   )*DD + k0 + akq);
        float4 a1 = *(const float4*)(A  + (size_t)(m0+arow+64)*DD + k0 + akq);
        float4 b0 = *(const float4*)(Bw + (size_t)(k0+kr  )*DD + n0 + nc);
        float4 b1 = *(const float4*)(Bw + (size_t)(k0+kr+8)*DD + n0 + nc);
        As[akq+0][arow]=a0.x; As[akq+1][arow]=a0.y; As[akq+2][arow]=a0.z; As[akq+3][arow]=a0.w;
        As[akq+0][arow+64]=a1.x; As[akq+1][arow+64]=a1.y; As[akq+2][arow+64]=a1.z; As[akq+3][arow+64]=a1.w;
        *(float4*)&Bs[kr  ][nc] = b0;
        *(float4*)&Bs[kr+8][nc] = b1;
        __syncthreads();
#pragma unroll
        for (int k=0;k<16;k++){
            float4 av0 = *(float4*)&As[k][ty*8];
            float4 av1 = *(float4*)&As[k][ty*8+4];
            float4 bv0 = *(float4*)&Bs[k][tx*8];
            float4 bv1 = *(float4*)&Bs[k][tx*8+4];
            float a[8] = {av0.x,av0.y,av0.z,av0.w,av1.x,av1.y,av1.z,av1.w};
            float bb[8]= {bv0.x,bv0.y,bv0.z,bv0.w,bv1.x,bv1.y,bv1.z,bv1.w};
#pragma unroll
            for (int i=0;i<8;i++)
#pragma unroll
                for (int j=0;j<8;j++) acc[i][j] += a[i]*bb[j];
        }
        __syncthreads();
    }
    float bl[8];
#pragma unroll
    for (int j=0;j<8;j++) bl[j] = bias[n0 + tx*8 + j];
#pragma unroll
    for (int i=0;i<8;i++){
        size_t o = (size_t)(m0 + ty*8 + i)*DD + n0 + tx*8;
        float4 o0 = {acc[i][0]+bl[0], acc[i][1]+bl[1], acc[i][2]+bl[2], acc[i][3]+bl[3]};
        float4 o1 = {acc[i][4]+bl[4], acc[i][5]+bl[5], acc[i][6]+bl[6], acc[i][7]+bl[7]};
        *(float4*)(C + o)     = o0;
        *(float4*)(C + o + 4) = o1;
    }
}

// ---------------- LN over each 1024-row + add broadcast cadd ------------------
__global__ void lnadd_kernel(float* __restrict__ buf,
    const float* __restrict__ g, const float* __restrict__ be,
    const float* __restrict__ cadd)
{
    __shared__ float red[256];
    int t = threadIdx.x;
    int r = blockIdx.x;          // 0..8191
    float4* row = (float4*)(buf + (size_t)r*DD);
    float4 v = row[t];
    float s = (v.x+v.y)+(v.z+v.w);
    red[t]=s; __syncthreads();
    for (int st=128;st>0;st>>=1){ if(t<st) red[t]+=red[t+st]; __syncthreads(); }
    float mu = red[0]*(1.0f/DD);
    __syncthreads();
    float dx=v.x-mu, dy=v.y-mu, dz=v.z-mu, dw=v.w-mu;
    float vv = (dx*dx+dy*dy)+(dz*dz+dw*dw);
    red[t]=vv; __syncthreads();
    for (int st=128;st>0;st>>=1){ if(t<st) red[t]+=red[t+st]; __syncthreads(); }
    float var = red[0]*(1.0f/DD);
    float rs = 1.0f/sqrtf(var + 1e-5f);
    const float4* g4  = (const float4*)g;
    const float4* be4 = (const float4*)be;
    const float4* ca4 = (const float4*)(cadd + (size_t)(r>>10)*DD);
    float4 gg=g4[t], bb=be4[t], cc=ca4[t];
    float4 o;
    o.x = dx*rs*gg.x + bb.x + cc.x;
    o.y = dy*rs*gg.y + bb.y + cc.y;
    o.z = dz*rs*gg.z + bb.z + cc.z;
    o.w = dw*rs*gg.w + bb.w + cc.w;
    row[t]=o;
}

// ---------------- QK^T per (b,h): 1024x1024, K=64, scale 512 -----------------
__global__ void __launch_bounds__(256) qk_kernel(
    const float* __restrict__ qb, const float* __restrict__ kb,
    float* __restrict__ attn)
{
    __shared__ float Qs[32][128];
    __shared__ float Ks[32][128];
    int t  = threadIdx.x;
    int bh = blockIdx.z;
    const float* qbase = qb + (size_t)(bh>>4)*SS*DD + (bh&15)*DKK;
    const float* kbase = kb + (size_t)(bh>>4)*SS*DD + (bh&15)*DKK;
    float* obase = attn + (size_t)bh*SS*SS;
    int m0 = blockIdx.y*128, n0 = blockIdx.x*128;
    int ty=t>>4, tx=t&15;
    int row = t&127, half = t>>7;

    float acc[8][8];
#pragma unroll
    for (int i=0;i<8;i++)
#pragma unroll
        for (int j=0;j<8;j++) acc[i][j]=0.f;

    for (int kk=0; kk<DKK; kk+=32){
#pragma unroll
        for (int i=0;i<4;i++){
            int dd = half*16 + i*4;
            float4 qv = *(const float4*)(qbase + (size_t)(m0+row)*DD + kk + dd);
            Qs[dd+0][row]=qv.x; Qs[dd+1][row]=qv.y; Qs[dd+2][row]=qv.z; Qs[dd+3][row]=qv.w;
            float4 kv = *(const float4*)(kbase + (size_t)(n0+row)*DD + kk + dd);
            Ks[dd+0][row]=kv.x; Ks[dd+1][row]=kv.y; Ks[dd+2][row]=kv.z; Ks[dd+3][row]=kv.w;
        }
        __syncthreads();
#pragma unroll
        for (int d=0; d<32; d++){
            float4 av0 = *(float4*)&Qs[d][ty*8];
            float4 av1 = *(float4*)&Qs[d][ty*8+4];
            float4 bv0 = *(float4*)&Ks[d][tx*8];
            float4 bv1 = *(float4*)&Ks[d][tx*8+4];
            float a[8] = {av0.x,av0.y,av0.z,av0.w,av1.x,av1.y,av1.z,av1.w};
            float bb[8]= {bv0.x,bv0.y,bv0.z,bv0.w,bv1.x,bv1.y,bv1.z,bv1.w};
#pragma unroll
            for (int i=0;i<8;i++)
#pragma unroll
                for (int j=0;j<8;j++) acc[i][j] += a[i]*bb[j];
        }
        __syncthreads();
    }
#pragma unroll
    for (int i=0;i<8;i++){
        size_t o = (size_t)(m0+ty*8+i)*SS + n0 + tx*8;
        float4 o0 = {acc[i][0]*SCALE_F, acc[i][1]*SCALE_F, acc[i][2]*SCALE_F, acc[i][3]*SCALE_F};
        float4 o1 = {acc[i][4]*SCALE_F, acc[i][5]*SCALE_F, acc[i][6]*SCALE_F, acc[i][7]*SCALE_F};
        *(float4*)(obase + o)     = o0;
        *(float4*)(obase + o + 4) = o1;
    }
}

// ---------------- softmax over each 1024-long row (in place) ------------------
__global__ void softmax_kernel(float* __restrict__ attn)
{
    __shared__ float red[256];
    int t = threadIdx.x;
    float4* p = (float4*)(attn + (size_t)blockIdx.x*SS);
    float4 v = p[t];
    float m = fmaxf(fmaxf(v.x,v.y), fmaxf(v.z,v.w));
    red[t]=m; __syncthreads();
    for (int st=128;st>0;st>>=1){ if(t<st) red[t]=fmaxf(red[t],red[t+st]); __syncthreads(); }
    m = red[0]; __syncthreads();
    float4 e;
    e.x = expf(v.x - m); e.y = expf(v.y - m);
    e.z = expf(v.z - m); e.w = expf(v.w - m);
    float s = (e.x+e.y)+(e.z+e.w);
    red[t]=s; __syncthreads();
    for (int st=128;st>0;st>>=1){ if(t<st) red[t]+=red[t+st]; __syncthreads(); }
    float tot = red[0];
    e.x = e.x/tot; e.y = e.y/tot; e.z = e.z/tot; e.w = e.w/tot;
    p[t]=e;
}

// ---------------- attn @ V per (b,h): (1024x1024)@(1024x64) ------------------
__global__ void __launch_bounds__(256) av_kernel(
    const float* __restrict__ attn, const float* __restrict__ vb,
    float* __restrict__ cx)
{
    __shared__ float Ps[32][128];   // transposed: Ps[k][m]
    __shared__ float Vs[32][64];
    int t = threadIdx.x;
    int bh = blockIdx.z;
    const float* pbase = attn + (size_t)bh*SS*SS;
    const float* vbase = vb + (size_t)(bh>>4)*SS*DD + (bh&15)*DKK;
    float* obase = cx + (size_t)(bh>>4)*SS*DD + (bh&15)*DKK;
    int m0 = blockIdx.y*128;
    int ty=t>>4, tx=t&15;
    int row=t&127, half=t>>7;
    int vkr = t>>4;       // 0..15 (second = +16)
    int vnc = (t&15)*4;   // 0..60

    float acc[8][4];
#pragma unroll
    for (int i=0;i<8;i++)
#pragma unroll
        for (int j=0;j<4;j++) acc[i][j]=0.f;

    for (int k0=0;k0<SS;k0+=32){
#pragma unroll
        for (int i=0;i<4;i++){
            int kq = half*16 + i*4;
            float4 pv = *(const float4*)(pbase + (size_t)(m0+row)*SS + k0 + kq);
            Ps[kq+0][row]=pv.x; Ps[kq+1][row]=pv.y; Ps[kq+2][row]=pv.z; Ps[kq+3][row]=pv.w;
        }
        float4 v0 = *(const float4*)(vbase + (size_t)(k0+vkr   )*DD + vnc);
        float4 v1 = *(const float4*)(vbase + (size_t)(k0+vkr+16)*DD + vnc);
        *(float4*)&Vs[vkr   ][vnc] = v0;
        *(float4*)&Vs[vkr+16][vnc] = v1;
        __syncthreads();
#pragma unroll
        for (int kk=0; kk<32; kk++){
            float4 av0 = *(float4*)&Ps[kk][ty*8];
            float4 av1 = *(float4*)&Ps[kk][ty*8+4];
            float4 bv  = *(float4*)&Vs[kk][tx*4];
            float a[8] = {av0.x,av0.y,av0.z,av0.w,av1.x,av1.y,av1.z,av1.w};
            float bb[4]= {bv.x,bv.y,bv.z,bv.w};
#pragma unroll
            for (int i=0;i<8;i++)
#pragma unroll
                for (int j=0;j<4;j++) acc[i][j] += a[i]*bb[j];
        }
        __syncthreads();
    }
#pragma unroll
    for (int i=0;i<8;i++){
        float4 o = {acc[i][0],acc[i][1],acc[i][2],acc[i][3]};
        *(float4*)(obase + (size_t)(m0+ty*8+i)*DD + tx*4) = o;
    }
}

// ------------------------------- launch ---------------------------------------
extern "C" void kernel_launch(void* const* d_in, const int* in_sizes, int n_in,
                              void* d_out, int out_size)
{
    const float* Q    = (const float*)d_in[0];
    const float* c    = (const float*)d_in[1];
    const float* Wq   = (const float*)d_in[2];
    const float* bq   = (const float*)d_in[3];
    const float* Wk   = (const float*)d_in[4];
    const float* bk   = (const float*)d_in[5];
    const float* Wv   = (const float*)d_in[6];
    const float* bv   = (const float*)d_in[7];
    const float* Wcq  = (const float*)d_in[8];
    const float* bcq  = (const float*)d_in[9];
    const float* Wck  = (const float*)d_in[10];
    const float* bck  = (const float*)d_in[11];
    const float* Wcv  = (const float*)d_in[12];
    const float* bcv  = (const float*)d_in[13];
    const float* g_q  = (const float*)d_in[14];
    const float* be_q = (const float*)d_in[15];
    const float* g_qc = (const float*)d_in[16];
    const float* be_qc= (const float*)d_in[17];
    const float* g_k  = (const float*)d_in[18];
    const float* be_k = (const float*)d_in[19];
    const float* g_kc = (const float*)d_in[20];
    const float* be_kc= (const float*)d_in[21];
    const float* g_v  = (const float*)d_in[22];
    const float* be_v = (const float*)d_in[23];
    const float* g_vc = (const float*)d_in[24];
    const float* be_vc= (const float*)d_in[25];
    const float* Wo   = (const float*)d_in[26];
    const float* bo   = (const float*)d_in[27];

    float* out  = (float*)d_out;
    float* attn = out + OUT_ELEMS;

    float *qb,*kb,*vb,*cx,*cadd;
    cudaGetSymbolAddress((void**)&qb,   d_qbuf);
    cudaGetSymbolAddress((void**)&kb,   d_kbuf);
    cudaGetSymbolAddress((void**)&vb,   d_vbuf);
    cudaGetSymbolAddress((void**)&cx,   d_ctxbuf);
    cudaGetSymbolAddress((void**)&cadd, d_caddbuf);

    // 1. conditioning branch projections + LN (tiny)
    cproj_kernel<<<dim3(3,BB),256>>>(c, Wcq,bcq, Wck,bck, Wcv,bcv,
                                     g_qc,be_qc, g_kc,be_kc, g_vc,be_vc, cadd);

    // 2. main projections (fp32 SGEMM)
    dim3 gg(DD/128, MT/128);
    sgemm_bias<<<gg,256>>>(Q, Wq, bq, qb);
    sgemm_bias<<<gg,256>>>(Q, Wk, bk, kb);
    sgemm_bias<<<gg,256>>>(Q, Wv, bv, vb);

    // 3. LayerNorm + broadcast add
    lnadd_kernel<<<MT,256>>>(qb, g_q, be_q, cadd + 0*BB*DD);
    lnadd_kernel<<<MT,256>>>(kb, g_k, be_k, cadd + 1*BB*DD);
    lnadd_kernel<<<MT,256>>>(vb, g_v, be_v, cadd + 2*BB*DD);

    // 4. scores = q4 k4^T * 512  (written into attn output region)
    qk_kernel<<<dim3(SS/128, SS/128, BB*HH),256>>>(qb, kb, attn);

    // 5. softmax rows (in place, attn is a checked output)
    softmax_kernel<<<BB*HH*SS,256>>>(attn);

    // 6. ctx = attn @ v4
    av_kernel<<<dim3(1, SS/128, BB*HH),256>>>(attn, vb, cx);

    // 7. out = ctx @ Wo + bo
    sgemm_bias<<<gg,256>>>(cx, Wo, bo, out);
}

// round 2
// speedup vs baseline: 1.0020x; 1.0020x over previous
#include <cuda_runtime.h>
#include <math.h>

#define BB   8
#define SS   1024
#define DD   1024
#define HH   16
#define DKK  64
#define CFF  256
#define MT   (BB*SS)          // 8192 rows
#define OUT_ELEMS  (MT*DD)    // 8388608
#define SCALE_F 512.0f

// ---------------- scratch (static device memory; no allocs allowed) -------------
__device__ float d_qbuf[MT*DD];
__device__ float d_kbuf[MT*DD];
__device__ float d_vbuf[MT*DD];
__device__ float d_ctxbuf[MT*DD];
__device__ float d_caddbuf[3*BB*DD];

// ---------------- small c-branch: y = LN(c @ Wc + b) --------------------------
__global__ void cproj_kernel(const float* __restrict__ c,
    const float* __restrict__ Wcq, const float* __restrict__ bcq,
    const float* __restrict__ Wck, const float* __restrict__ bck,
    const float* __restrict__ Wcv, const float* __restrict__ bcv,
    const float* __restrict__ gqc, const float* __restrict__ beqc,
    const float* __restrict__ gkc, const float* __restrict__ bekc,
    const float* __restrict__ gvc, const float* __restrict__ bevc,
    float* __restrict__ cadd)
{
    int p = blockIdx.x;   // 0=q,1=k,2=v
    int b = blockIdx.y;
    int t = threadIdx.x;  // 256
    const float* W  = (p==0)?Wcq:((p==1)?Wck:Wcv);
    const float* bi = (p==0)?bcq:((p==1)?bck:bcv);
    const float* g  = (p==0)?gqc:((p==1)?gkc:gvc);
    const float* be = (p==0)?beqc:((p==1)?bekc:bevc);

    __shared__ float sc[CFF];
    __shared__ float red[256];
    sc[t] = c[b*CFF + t];
    __syncthreads();

    float y[4];
#pragma unroll
    for (int jj=0;jj<4;jj++){
        int j = jj*256 + t;
        float acc = bi[j];
        for (int i=0;i<CFF;i++) acc += sc[i]*W[(size_t)i*DD + j];
        y[jj]=acc;
    }
    float s = (y[0]+y[1])+(y[2]+y[3]);
    red[t]=s; __syncthreads();
    for (int st=128;st>0;st>>=1){ if(t<st) red[t]+=red[t+st]; __syncthreads(); }
    float mu = red[0]*(1.0f/DD);
    __syncthreads();
    float vv=0.f;
#pragma unroll
    for (int jj=0;jj<4;jj++){ float d0=y[jj]-mu; vv += d0*d0; }
    red[t]=vv; __syncthreads();
    for (int st=128;st>0;st>>=1){ if(t<st) red[t]+=red[t+st]; __syncthreads(); }
    float var = red[0]*(1.0f/DD);
    float rs = 1.0f/sqrtf(var + 1e-5f);
#pragma unroll
    for (int jj=0;jj<4;jj++){
        int j = jj*256 + t;
        cadd[(size_t)(p*BB + b)*DD + j] = (y[jj]-mu)*rs*g[j] + be[j];
    }
}

// ---------------- fp32 SGEMM: C[M=8192][1024] = A @ Bw + bias -----------------
// BM=BN=128, BK=16, 256 threads, 8x8 microtile
__global__ void __launch_bounds__(256) sgemm_bias(
    const float* __restrict__ A, const float* __restrict__ Bw,
    const float* __restrict__ bias, float* __restrict__ C)
{
    __shared__ float As[16][128];
    __shared__ float Bs[16][128];
    int t  = threadIdx.x;
    int m0 = blockIdx.y*128, n0 = blockIdx.x*128;
    int ty = t>>4, tx = t&15;

    float acc[8][8];
#pragma unroll
    for (int i=0;i<8;i++)
#pragma unroll
        for (int j=0;j<8;j++) acc[i][j]=0.f;

    int arow = t>>2;            // 0..63 (second load = +64)
    int akq  = (t&3)*4;         // 0,4,8,12
    int kr   = t>>5;            // 0..7 (second load = +8)
    int nc   = (t&31)*4;        // 0..124

    for (int k0=0;k0<DD;k0+=16){
        float4 a0 = *(const float4*)(A  + (size_t)(m0+arow   )*DD + k0 + akq);
        float4 a1 = *(const float4*)(A  + (size_t)(m0+arow+64)*DD + k0 + akq);
        float4 b0 = *(const float4*)(Bw + (size_t)(k0+kr  )*DD + n0 + nc);
        float4 b1 = *(const float4*)(Bw + (size_t)(k0+kr+8)*DD + n0 + nc);
        As[akq+0][arow]=a0.x; As[akq+1][arow]=a0.y; As[akq+2][arow]=a0.z; As[akq+3][arow]=a0.w;
        As[akq+0][arow+64]=a1.x; As[akq+1][arow+64]=a1.y; As[akq+2][arow+64]=a1.z; As[akq+3][arow+64]=a1.w;
        *(float4*)&Bs[kr  ][nc] = b0;
        *(float4*)&Bs[kr+8][nc] = b1;
        __syncthreads();
#pragma unroll
        for (int k=0;k<16;k++){
            float4 av0 = *(float4*)&As[k][ty*8];
            float4 av1 = *(float4*)&As[k][ty*8+4];
            float4 bv0 = *(float4*)&Bs[k][tx*8];
            float4 bv1 = *(float4*)&Bs[k][tx*8+4];
            float a[8] = {av0.x,av0.y,av0.z,av0.w,av1.x,av1.y,av1.z,av1.w};
            float bb[8]= {bv0.x,bv0.y,bv0.z,bv0.w,bv1.x,bv1.y,bv1.z,bv1.w};
#pragma unroll
            for (int i=0;i<8;i++)
#pragma unroll
                for (int j=0;j<8;j++) acc[i][j] += a[i]*bb[j];
        }
        __syncthreads();
    }
    float bl[8];
#pragma unroll
    for (int j=0;j<8;j++) bl[j] = bias[n0 + tx*8 + j];
#pragma unroll
    for (int i=0;i<8;i++){
        size_t o = (size_t)(m0 + ty*8 + i)*DD + n0 + tx*8;
        float4 o0 = {acc[i][0]+bl[0], acc[i][1]+bl[1], acc[i][2]+bl[2], acc[i][3]+bl[3]};
        float4 o1 = {acc[i][4]+bl[4], acc[i][5]+bl[5], acc[i][6]+bl[6], acc[i][7]+bl[7]};
        *(float4*)(C + o)     = o0;
        *(float4*)(C + o + 4) = o1;
    }
}

// ---------------- LN over each 1024-row + add broadcast cadd ------------------
__global__ void lnadd_kernel(float* __restrict__ buf,
    const float* __restrict__ g, const float* __restrict__ be,
    const float* __restrict__ cadd)
{
    __shared__ float red[256];
    int t = threadIdx.x;
    int r = blockIdx.x;          // 0..8191
    float4* row = (float4*)(buf + (size_t)r*DD);
    float4 v = row[t];
    float s = (v.x+v.y)+(v.z+v.w);
    red[t]=s; __syncthreads();
    for (int st=128;st>0;st>>=1){ if(t<st) red[t]+=red[t+st]; __syncthreads(); }
    float mu = red[0]*(1.0f/DD);
    __syncthreads();
    float dx=v.x-mu, dy=v.y-mu, dz=v.z-mu, dw=v.w-mu;
    float vv = (dx*dx+dy*dy)+(dz*dz+dw*dw);
    red[t]=vv; __syncthreads();
    for (int st=128;st>0;st>>=1){ if(t<st) red[t]+=red[t+st]; __syncthreads(); }
    float var = red[0]*(1.0f/DD);
    float rs = 1.0f/sqrtf(var + 1e-5f);
    const float4* g4  = (const float4*)g;
    const float4* be4 = (const float4*)be;
    const float4* ca4 = (const float4*)(cadd + (size_t)(r>>10)*DD);
    float4 gg=g4[t], bb=be4[t], cc=ca4[t];
    float4 o;
    o.x = dx*rs*gg.x + bb.x + cc.x;
    o.y = dy*rs*gg.y + bb.y + cc.y;
    o.z = dz*rs*gg.z + bb.z + cc.z;
    o.w = dw*rs*gg.w + bb.w + cc.w;
    row[t]=o;
}

// ---------------- QK^T per (b,h): 1024x1024, K=64, scale 512 -----------------
__global__ void __launch_bounds__(256) qk_kernel(
    const float* __restrict__ qb, const float* __restrict__ kb,
    float* __restrict__ attn)
{
    __shared__ float Qs[32][128];
    __shared__ float Ks[32][128];
    int t  = threadIdx.x;
    int bh = blockIdx.z;
    const float* qbase = qb + (size_t)(bh>>4)*SS*DD + (bh&15)*DKK;
    const float* kbase = kb + (size_t)(bh>>4)*SS*DD + (bh&15)*DKK;
    float* obase = attn + (size_t)bh*SS*SS;
    int m0 = blockIdx.y*128, n0 = blockIdx.x*128;
    int ty=t>>4, tx=t&15;
    int row = t&127, half = t>>7;

    float acc[8][8];
#pragma unroll
    for (int i=0;i<8;i++)
#pragma unroll
        for (int j=0;j<8;j++) acc[i][j]=0.f;

    for (int kk=0; kk<DKK; kk+=32){
#pragma unroll
        for (int i=0;i<4;i++){
            int dd = half*16 + i*4;
            float4 qv = *(const float4*)(qbase + (size_t)(m0+row)*DD + kk + dd);
            Qs[dd+0][row]=qv.x; Qs[dd+1][row]=qv.y; Qs[dd+2][row]=qv.z; Qs[dd+3][row]=qv.w;
            float4 kv = *(const float4*)(kbase + (size_t)(n0+row)*DD + kk + dd);
            Ks[dd+0][row]=kv.x; Ks[dd+1][row]=kv.y; Ks[dd+2][row]=kv.z; Ks[dd+3][row]=kv.w;
        }
        __syncthreads();
#pragma unroll
        for (int d=0; d<32; d++){
            float4 av0 = *(float4*)&Qs[d][ty*8];
            float4 av1 = *(float4*)&Qs[d][ty*8+4];
            float4 bv0 = *(float4*)&Ks[d][tx*8];
            float4 bv1 = *(float4*)&Ks[d][tx*8+4];
            float a[8] = {av0.x,av0.y,av0.z,av0.w,av1.x,av1.y,av1.z,av1.w};
            float bb[8]= {bv0.x,bv0.y,bv0.z,bv0.w,bv1.x,bv1.y,bv1.z,bv1.w};
#pragma unroll
            for (int i=0;i<8;i++)
#pragma unroll
                for (int j=0;j<8;j++) acc[i][j] += a[i]*bb[j];
        }
        __syncthreads();
    }
#pragma unroll
    for (int i=0;i<8;i++){
        size_t o = (size_t)(m0+ty*8+i)*SS + n0 + tx*8;
        float4 o0 = {acc[i][0]*SCALE_F, acc[i][1]*SCALE_F, acc[i][2]*SCALE_F, acc[i][3]*SCALE_F};
        float4 o1 = {acc[i][4]*SCALE_F, acc[i][5]*SCALE_F, acc[i][6]*SCALE_F, acc[i][7]*SCALE_F};
        *(float4*)(obase + o)     = o0;
        *(float4*)(obase + o + 4) = o1;
    }
}

// ---------------- softmax over each 1024-long row (in place) ------------------
__global__ void softmax_kernel(float* __restrict__ attn)
{
    __shared__ float red[256];
    int t = threadIdx.x;
    float4* p = (float4*)(attn + (size_t)blockIdx.x*SS);
    float4 v = p[t];
    float m = fmaxf(fmaxf(v.x,v.y), fmaxf(v.z,v.w));
    red[t]=m; __syncthreads();
    for (int st=128;st>0;st>>=1){ if(t<st) red[t]=fmaxf(red[t],red[t+st]); __syncthreads(); }
    m = red[0]; __syncthreads();
    float4 e;
    e.x = expf(v.x - m); e.y = expf(v.y - m);
    e.z = expf(v.z - m); e.w = expf(v.w - m);
    float s = (e.x+e.y)+(e.z+e.w);
    red[t]=s; __syncthreads();
    for (int st=128;st>0;st>>=1){ if(t<st) red[t]+=red[t+st]; __syncthreads(); }
    float tot = red[0];
    e.x = e.x/tot; e.y = e.y/tot; e.z = e.z/tot; e.w = e.w/tot;
    p[t]=e;
}

// ---------------- attn @ V per (b,h): (1024x1024)@(1024x64) ------------------
__global__ void __launch_bounds__(256) av_kernel(
    const float* __restrict__ attn, const float* __restrict__ vb,
    float* __restrict__ cx)
{
    __shared__ float Ps[32][128];   // transposed: Ps[k][m]
    __shared__ float Vs[32][64];
    int t = threadIdx.x;
    int bh = blockIdx.z;
    const float* pbase = attn + (size_t)bh*SS*SS;
    const float* vbase = vb + (size_t)(bh>>4)*SS*DD + (bh&15)*DKK;
    float* obase = cx + (size_t)(bh>>4)*SS*DD + (bh&15)*DKK;
    int m0 = blockIdx.y*128;
    int ty=t>>4, tx=t&15;
    int row=t&127, half=t>>7;
    int vkr = t>>4;       // 0..15 (second = +16)
    int vnc = (t&15)*4;   // 0..60

    float acc[8][4];
#pragma unroll
    for (int i=0;i<8;i++)
#pragma unroll
        for (int j=0;j<4;j++) acc[i][j]=0.f;

    for (int k0=0;k0<SS;k0+=32){
#pragma unroll
        for (int i=0;i<4;i++){
            int kq = half*16 + i*4;
            float4 pv = *(const float4*)(pbase + (size_t)(m0+row)*SS + k0 + kq);
            Ps[kq+0][row]=pv.x; Ps[kq+1][row]=pv.y; Ps[kq+2][row]=pv.z; Ps[kq+3][row]=pv.w;
        }
        float4 v0 = *(const float4*)(vbase + (size_t)(k0+vkr   )*DD + vnc);
        float4 v1 = *(const float4*)(vbase + (size_t)(k0+vkr+16)*DD + vnc);
        *(float4*)&Vs[vkr   ][vnc] = v0;
        *(float4*)&Vs[vkr+16][vnc] = v1;
        __syncthreads();
#pragma unroll
        for (int kk=0; kk<32; kk++){
            float4 av0 = *(float4*)&Ps[kk][ty*8];
            float4 av1 = *(float4*)&Ps[kk][ty*8+4];
            float4 bv  = *(float4*)&Vs[kk][tx*4];
            float a[8] = {av0.x,av0.y,av0.z,av0.w,av1.x,av1.y,av1.z,av1.w};
            float bb[4]= {bv.x,bv.y,bv.z,bv.w};
#pragma unroll
            for (int i=0;i<8;i++)
#pragma unroll
                for (int j=0;j<4;j++) acc[i][j] += a[i]*bb[j];
        }
        __syncthreads();
    }
#pragma unroll
    for (int i=0;i<8;i++){
        float4 o = {acc[i][0],acc[i][1],acc[i][2],acc[i][3]};
        *(float4*)(obase + (size_t)(m0+ty*8+i)*DD + tx*4) = o;
    }
}

// ------------------------------- launch ---------------------------------------
extern "C" void kernel_launch(void* const* d_in, const int* in_sizes, int n_in,
                              void* d_out, int out_size)
{
    const float* Q    = (const float*)d_in[0];
    const float* c    = (const float*)d_in[1];
    const float* Wq   = (const float*)d_in[2];
    const float* bq   = (const float*)d_in[3];
    const float* Wk   = (const float*)d_in[4];
    const float* bk   = (const float*)d_in[5];
    const float* Wv   = (const float*)d_in[6];
    const float* bv   = (const float*)d_in[7];
    const float* Wcq  = (const float*)d_in[8];
    const float* bcq  = (const float*)d_in[9];
    const float* Wck  = (const float*)d_in[10];
    const float* bck  = (const float*)d_in[11];
    const float* Wcv  = (const float*)d_in[12];
    const float* bcv  = (const float*)d_in[13];
    const float* g_q  = (const float*)d_in[14];
    const float* be_q = (const float*)d_in[15];
    const float* g_qc = (const float*)d_in[16];
    const float* be_qc= (const float*)d_in[17];
    const float* g_k  = (const float*)d_in[18];
    const float* be_k = (const float*)d_in[19];
    const float* g_kc = (const float*)d_in[20];
    const float* be_kc= (const float*)d_in[21];
    const float* g_v  = (const float*)d_in[22];
    const float* be_v = (const float*)d_in[23];
    const float* g_vc = (const float*)d_in[24];
    const float* be_vc= (const float*)d_in[25];
    const float* Wo   = (const float*)d_in[26];
    const float* bo   = (const float*)d_in[27];

    float* out  = (float*)d_out;
    float* attn = out + OUT_ELEMS;

    float *qb,*kb,*vb,*cx,*cadd;
    cudaGetSymbolAddress((void**)&qb,   d_qbuf);
    cudaGetSymbolAddress((void**)&kb,   d_kbuf);
    cudaGetSymbolAddress((void**)&vb,   d_vbuf);
    cudaGetSymbolAddress((void**)&cx,   d_ctxbuf);
    cudaGetSymbolAddress((void**)&cadd, d_caddbuf);

    // 1. conditioning branch projections + LN (tiny)
    cproj_kernel<<<dim3(3,BB),256>>>(c, Wcq,bcq, Wck,bck, Wcv,bcv,
                                     g_qc,be_qc, g_kc,be_kc, g_vc,be_vc, cadd);

    // 2. main projections (fp32 SGEMM)
    dim3 gg(DD/128, MT/128);
    sgemm_bias<<<gg,256>>>(Q, Wq, bq, qb);
    sgemm_bias<<<gg,256>>>(Q, Wk, bk, kb);
    sgemm_bias<<<gg,256>>>(Q, Wv, bv, vb);

    // 3. LayerNorm + broadcast add
    lnadd_kernel<<<MT,256>>>(qb, g_q, be_q, cadd + 0*BB*DD);
    lnadd_kernel<<<MT,256>>>(kb, g_k, be_k, cadd + 1*BB*DD);
    lnadd_kernel<<<MT,256>>>(vb, g_v, be_v, cadd + 2*BB*DD);

    // 4. scores = q4 k4^T * 512  (written into attn output region)
    qk_kernel<<<dim3(SS/128, SS/128, BB*HH),256>>>(qb, kb, attn);

    // 5. softmax rows (in place, attn is a checked output)
    softmax_kernel<<<BB*HH*SS,256>>>(attn);

    // 6. ctx = attn @ v4
    av_kernel<<<dim3(1, SS/128, BB*HH),256>>>(attn, vb, cx);

    // 7. out = ctx @ Wo + bo
    sgemm_bias<<<gg,256>>>(cx, Wo, bo, out);
}

// round 3
// speedup vs baseline: 1.0132x; 1.0112x over previous
#include <cuda_runtime.h>
#include <math.h>

#define BB   8
#define SS   1024
#define DD   1024
#define HH   16
#define DKK  64
#define CFF  256
#define MT   (BB*SS)
#define OUT_ELEMS  (MT*DD)
#define SCALE_F 512.0f

typedef unsigned long long ull;

__device__ float d_qbuf[MT*DD];
__device__ float d_kbuf[MT*DD];
__device__ float d_vbuf[MT*DD];
__device__ float d_ctxbuf[MT*DD];
__device__ float d_caddbuf[3*BB*DD];

__device__ __forceinline__ ull pack2(float lo, float hi){
    ull r; asm("mov.b64 %0, {%1, %2};" : "=l"(r) : "f"(lo), "f"(hi)); return r;
}
__device__ __forceinline__ void fma2(ull& d, ull a, ull b){
    asm("fma.rn.f32x2 %0, %1, %2, %0;" : "+l"(d) : "l"(a), "l"(b));
}
__device__ __forceinline__ float2 unpack2(ull v){
    float2 r; asm("mov.b64 {%0, %1}, %2;" : "=f"(r.x), "=f"(r.y) : "l"(v)); return r;
}

// ---------------- small c-branch: y = LN(c @ Wc + b) --------------------------
__global__ void cproj_kernel(const float* __restrict__ c,
    const float* __restrict__ Wcq, const float* __restrict__ bcq,
    const float* __restrict__ Wck, const float* __restrict__ bck,
    const float* __restrict__ Wcv, const float* __restrict__ bcv,
    const float* __restrict__ gqc, const float* __restrict__ beqc,
    const float* __restrict__ gkc, const float* __restrict__ bekc,
    const float* __restrict__ gvc, const float* __restrict__ bevc,
    float* __restrict__ cadd)
{
    int p = blockIdx.x, b = blockIdx.y, t = threadIdx.x;
    const float* W  = (p==0)?Wcq:((p==1)?Wck:Wcv);
    const float* bi = (p==0)?bcq:((p==1)?bck:bcv);
    const float* g  = (p==0)?gqc:((p==1)?gkc:gvc);
    const float* be = (p==0)?beqc:((p==1)?bekc:bevc);

    __shared__ float sc[CFF];
    __shared__ float red[256];
    sc[t] = c[b*CFF + t];
    __syncthreads();

    float y[4];
#pragma unroll
    for (int jj=0;jj<4;jj++){
        int j = jj*256 + t;
        float acc = bi[j];
        for (int i=0;i<CFF;i++) acc += sc[i]*W[(size_t)i*DD + j];
        y[jj]=acc;
    }
    float s = (y[0]+y[1])+(y[2]+y[3]);
    red[t]=s; __syncthreads();
    for (int st=128;st>0;st>>=1){ if(t<st) red[t]+=red[t+st]; __syncthreads(); }
    float mu = red[0]*(1.0f/DD);
    __syncthreads();
    float vv=0.f;
#pragma unroll
    for (int jj=0;jj<4;jj++){ float d0=y[jj]-mu; vv += d0*d0; }
    red[t]=vv; __syncthreads();
    for (int st=128;st>0;st>>=1){ if(t<st) red[t]+=red[t+st]; __syncthreads(); }
    float rs = 1.0f/sqrtf(red[0]*(1.0f/DD) + 1e-5f);
#pragma unroll
    for (int jj=0;jj<4;jj++){
        int j = jj*256 + t;
        cadd[(size_t)(p*BB + b)*DD + j] = (y[jj]-mu)*rs*g[j] + be[j];
    }
}

// ------- fp32 SGEMM 128x128, BK=16, double-buffered, FFMA2 microtile ---------
__global__ void __launch_bounds__(256) sgemm_bias(
    const float* __restrict__ A, const float* __restrict__ Bw,
    const float* __restrict__ bias, float* __restrict__ C)
{
    __shared__ float As[2][16][128];
    __shared__ float Bs[2][16][128];
    int t  = threadIdx.x;
    int m0 = blockIdx.y*128, n0 = blockIdx.x*128;
    int ty = t>>4, tx = t&15;
    int arow = t>>2, akq = (t&3)*4;
    int kr = t>>5,   nc  = (t&31)*4;

    const float* Ap  = A  + (size_t)(m0+arow)*DD + akq;
    const float* Ap2 = Ap + (size_t)64*DD;
    const float* Bp  = Bw + (size_t)kr*DD + n0 + nc;

    {   // stage 0 preload
        float4 a0=*(const float4*)Ap, a1=*(const float4*)Ap2;
        float4 b0=*(const float4*)Bp, b1=*(const float4*)(Bp+(size_t)8*DD);
        As[0][akq+0][arow]=a0.x; As[0][akq+1][arow]=a0.y; As[0][akq+2][arow]=a0.z; As[0][akq+3][arow]=a0.w;
        As[0][akq+0][arow+64]=a1.x; As[0][akq+1][arow+64]=a1.y; As[0][akq+2][arow+64]=a1.z; As[0][akq+3][arow+64]=a1.w;
        *(float4*)&Bs[0][kr  ][nc]=b0;
        *(float4*)&Bs[0][kr+8][nc]=b1;
    }
    __syncthreads();

    ull acc[8][4];
#pragma unroll
    for (int r=0;r<8;r++)
#pragma unroll
        for (int g=0;g<4;g++) acc[r][g]=0ULL;

    for (int k0=16;k0<=DD;k0+=16){
        int cur = ((k0>>4)-1)&1;
        bool more = (k0 < DD);
        float4 na0,na1,nb0,nb1;
        if (more){
            na0=*(const float4*)(Ap +k0);
            na1=*(const float4*)(Ap2+k0);
            nb0=*(const float4*)(Bp+(size_t)k0*DD);
            nb1=*(const float4*)(Bp+(size_t)(k0+8)*DD);
        }
#pragma unroll
        for (int k=0;k<16;k++){
            float4 av0 = *(float4*)&As[cur][k][ty*8];
            float4 av1 = *(float4*)&As[cur][k][ty*8+4];
            ulonglong2 bl0 = *(ulonglong2*)&Bs[cur][k][tx*8];
            ulonglong2 bl1 = *(ulonglong2*)&Bs[cur][k][tx*8+4];
            ull aa[8];
            aa[0]=pack2(av0.x,av0.x); aa[1]=pack2(av0.y,av0.y);
            aa[2]=pack2(av0.z,av0.z); aa[3]=pack2(av0.w,av0.w);
            aa[4]=pack2(av1.x,av1.x); aa[5]=pack2(av1.y,av1.y);
            aa[6]=pack2(av1.z,av1.z); aa[7]=pack2(av1.w,av1.w);
#pragma unroll
            for (int r=0;r<8;r++){
                fma2(acc[r][0],aa[r],bl0.x);
                fma2(acc[r][1],aa[r],bl0.y);
                fma2(acc[r][2],aa[r],bl1.x);
                fma2(acc[r][3],aa[r],bl1.y);
            }
        }
        if (more){
            int nx = cur^1;
            As[nx][akq+0][arow]=na0.x; As[nx][akq+1][arow]=na0.y; As[nx][akq+2][arow]=na0.z; As[nx][akq+3][arow]=na0.w;
            As[nx][akq+0][arow+64]=na1.x; As[nx][akq+1][arow+64]=na1.y; As[nx][akq+2][arow+64]=na1.z; As[nx][akq+3][arow+64]=na1.w;
            *(float4*)&Bs[nx][kr  ][nc]=nb0;
            *(float4*)&Bs[nx][kr+8][nc]=nb1;
        }
        __syncthreads();
    }

    float4 bl = *(const float4*)(bias + n0 + tx*8);
    float4 bh = *(const float4*)(bias + n0 + tx*8 + 4);
#pragma unroll
    for (int r=0;r<8;r++){
        float2 u0=unpack2(acc[r][0]), u1=unpack2(acc[r][1]);
        float2 u2=unpack2(acc[r][2]), u3=unpack2(acc[r][3]);
        size_t o = (size_t)(m0+ty*8+r)*DD + n0 + tx*8;
        float4 o0 = {u0.x+bl.x, u0.y+bl.y, u1.x+bl.z, u1.y+bl.w};
        float4 o1 = {u2.x+bh.x, u2.y+bh.y, u3.x+bh.z, u3.y+bh.w};
        *(float4*)(C+o) = o0; *(float4*)(C+o+4) = o1;
    }
}

// ---------------- LN over each 1024-row + add broadcast cadd ------------------
__global__ void lnadd_kernel(float* __restrict__ buf,
    const float* __restrict__ g, const float* __restrict__ be,
    const float* __restrict__ cadd)
{
    __shared__ float red[256];
    int t = threadIdx.x, r = blockIdx.x;
    float4* row = (float4*)(buf + (size_t)r*DD);
    float4 v = row[t];
    float s = (v.x+v.y)+(v.z+v.w);
    red[t]=s; __syncthreads();
    for (int st=128;st>0;st>>=1){ if(t<st) red[t]+=red[t+st]; __syncthreads(); }
    float mu = red[0]*(1.0f/DD);
    __syncthreads();
    float dx=v.x-mu, dy=v.y-mu, dz=v.z-mu, dw=v.w-mu;
    red[t]=(dx*dx+dy*dy)+(dz*dz+dw*dw); __syncthreads();
    for (int st=128;st>0;st>>=1){ if(t<st) red[t]+=red[t+st]; __syncthreads(); }
    float rs = 1.0f/sqrtf(red[0]*(1.0f/DD) + 1e-5f);
    float4 gg=((const float4*)g)[t], bb=((const float4*)be)[t];
    float4 cc=((const float4*)(cadd+(size_t)(r>>10)*DD))[t];
    float4 o = {dx*rs*gg.x+bb.x+cc.x, dy*rs*gg.y+bb.y+cc.y,
                dz*rs*gg.z+bb.z+cc.z, dw*rs*gg.w+bb.w+cc.w};
    row[t]=o;
}

// ---------------- QK^T per (b,h): 1024x1024, K=64, scale 512, FFMA2 ----------
__global__ void __launch_bounds__(256) qk_kernel(
    const float* __restrict__ qb, const float* __restrict__ kb,
    float* __restrict__ attn)
{
    __shared__ float Qs[32][128];
    __shared__ float Ks[32][128];
    int t  = threadIdx.x, bh = blockIdx.z;
    const float* qbase = qb + (size_t)(bh>>4)*SS*DD + (bh&15)*DKK;
    const float* kbase = kb + (size_t)(bh>>4)*SS*DD + (bh&15)*DKK;
    float* obase = attn + (size_t)bh*SS*SS;
    int m0 = blockIdx.y*128, n0 = blockIdx.x*128;
    int ty=t>>4, tx=t&15;
    int row=t&127, half=t>>7;

    ull acc[8][4];
#pragma unroll
    for (int r=0;r<8;r++)
#pragma unroll
        for (int g=0;g<4;g++) acc[r][g]=0ULL;

    for (int kk=0; kk<DKK; kk+=32){
#pragma unroll
        for (int i=0;i<4;i++){
            int dd = half*16 + i*4;
            float4 qv = *(const float4*)(qbase + (size_t)(m0+row)*DD + kk + dd);
            Qs[dd+0][row]=qv.x; Qs[dd+1][row]=qv.y; Qs[dd+2][row]=qv.z; Qs[dd+3][row]=qv.w;
            float4 kv = *(const float4*)(kbase + (size_t)(n0+row)*DD + kk + dd);
            Ks[dd+0][row]=kv.x; Ks[dd+1][row]=kv.y; Ks[dd+2][row]=kv.z; Ks[dd+3][row]=kv.w;
        }
        __syncthreads();
#pragma unroll
        for (int d=0; d<32; d++){
            float4 av0 = *(float4*)&Qs[d][ty*8];
            float4 av1 = *(float4*)&Qs[d][ty*8+4];
            ulonglong2 bl0 = *(ulonglong2*)&Ks[d][tx*8];
            ulonglong2 bl1 = *(ulonglong2*)&Ks[d][tx*8+4];
            ull aa[8];
            aa[0]=pack2(av0.x,av0.x); aa[1]=pack2(av0.y,av0.y);
            aa[2]=pack2(av0.z,av0.z); aa[3]=pack2(av0.w,av0.w);
            aa[4]=pack2(av1.x,av1.x); aa[5]=pack2(av1.y,av1.y);
            aa[6]=pack2(av1.z,av1.z); aa[7]=pack2(av1.w,av1.w);
#pragma unroll
            for (int r=0;r<8;r++){
                fma2(acc[r][0],aa[r],bl0.x);
                fma2(acc[r][1],aa[r],bl0.y);
                fma2(acc[r][2],aa[r],bl1.x);
                fma2(acc[r][3],aa[r],bl1.y);
            }
        }
        __syncthreads();
    }
#pragma unroll
    for (int r=0;r<8;r++){
        float2 u0=unpack2(acc[r][0]), u1=unpack2(acc[r][1]);
        float2 u2=unpack2(acc[r][2]), u3=unpack2(acc[r][3]);
        size_t o = (size_t)(m0+ty*8+r)*SS + n0 + tx*8;
        float4 o0 = {u0.x*SCALE_F,u0.y*SCALE_F,u1.x*SCALE_F,u1.y*SCALE_F};
        float4 o1 = {u2.x*SCALE_F,u2.y*SCALE_F,u3.x*SCALE_F,u3.y*SCALE_F};
        *(float4*)(obase+o)=o0; *(float4*)(obase+o+4)=o1;
    }
}

// ---------------- softmax over each 1024-long row (in place) ------------------
__global__ void softmax_kernel(float* __restrict__ attn)
{
    __shared__ float red[256];
    int t = threadIdx.x;
    float4* p = (float4*)(attn + (size_t)blockIdx.x*SS);
    float4 v = p[t];
    float m = fmaxf(fmaxf(v.x,v.y), fmaxf(v.z,v.w));
    red[t]=m; __syncthreads();
    for (int st=128;st>0;st>>=1){ if(t<st) red[t]=fmaxf(red[t],red[t+st]); __syncthreads(); }
    m = red[0]; __syncthreads();
    float4 e = {expf(v.x-m), expf(v.y-m), expf(v.z-m), expf(v.w-m)};
    red[t]=(e.x+e.y)+(e.z+e.w); __syncthreads();
    for (int st=128;st>0;st>>=1){ if(t<st) red[t]+=red[t+st]; __syncthreads(); }
    float inv = 1.0f/red[0];
    e.x*=inv; e.y*=inv; e.z*=inv; e.w*=inv;
    p[t]=e;
}

// ---------------- attn @ V per (b,h), FFMA2 -----------------------------------
__global__ void __launch_bounds__(256) av_kernel(
    const float* __restrict__ attn, const float* __restrict__ vb,
    float* __restrict__ cx)
{
    __shared__ float Ps[32][128];
    __shared__ float Vs[32][64];
    int t = threadIdx.x, bh = blockIdx.z;
    const float* pbase = attn + (size_t)bh*SS*SS;
    const float* vbase = vb + (size_t)(bh>>4)*SS*DD + (bh&15)*DKK;
    float* obase = cx + (size_t)(bh>>4)*SS*DD + (bh&15)*DKK;
    int m0 = blockIdx.y*128;
    int ty=t>>4, tx=t&15;
    int row=t&127, half=t>>7;
    int vkr=t>>4, vnc=(t&15)*4;

    ull acc[8][2];
#pragma unroll
    for (int r=0;r<8;r++){ acc[r][0]=0ULL; acc[r][1]=0ULL; }

    for (int k0=0;k0<SS;k0+=32){
#pragma unroll
        for (int i=0;i<4;i++){
            int kq = half*16 + i*4;
            float4 pv = *(const float4*)(pbase + (size_t)(m0+row)*SS + k0 + kq);
            Ps[kq+0][row]=pv.x; Ps[kq+1][row]=pv.y; Ps[kq+2][row]=pv.z; Ps[kq+3][row]=pv.w;
        }
        float4 v0 = *(const float4*)(vbase + (size_t)(k0+vkr   )*DD + vnc);
        float4 v1 = *(const float4*)(vbase + (size_t)(k0+vkr+16)*DD + vnc);
        *(float4*)&Vs[vkr   ][vnc]=v0;
        *(float4*)&Vs[vkr+16][vnc]=v1;
        __syncthreads();
#pragma unroll
        for (int kk=0; kk<32; kk++){
            float4 av0 = *(float4*)&Ps[kk][ty*8];
            float4 av1 = *(float4*)&Ps[kk][ty*8+4];
            ulonglong2 bv = *(ulonglong2*)&Vs[kk][tx*4];
            ull aa[8];
            aa[0]=pack2(av0.x,av0.x); aa[1]=pack2(av0.y,av0.y);
            aa[2]=pack2(av0.z,av0.z); aa[3]=pack2(av0.w,av0.w);
            aa[4]=pack2(av1.x,av1.x); aa[5]=pack2(av1.y,av1.y);
            aa[6]=pack2(av1.z,av1.z); aa[7]=pack2(av1.w,av1.w);
#pragma unroll
            for (int r=0;r<8;r++){
                fma2(acc[r][0],aa[r],bv.x);
                fma2(acc[r][1],aa[r],bv.y);
            }
        }
        __syncthreads();
    }
#pragma unroll
    for (int r=0;r<8;r++){
        float2 u0=unpack2(acc[r][0]), u1=unpack2(acc[r][1]);
        float4 o = {u0.x,u0.y,u1.x,u1.y};
        *(float4*)(obase + (size_t)(m0+ty*8+r)*DD + tx*4) = o;
    }
}

// ------------------------------- launch ---------------------------------------
extern "C" void kernel_launch(void* const* d_in, const int* in_sizes, int n_in,
                              void* d_out, int out_size)
{
    const float* Q    = (const float*)d_in[0];
    const float* c    = (const float*)d_in[1];
    const float* Wq   = (const float*)d_in[2];
    const float* bq   = (const float*)d_in[3];
    const float* Wk   = (const float*)d_in[4];
    const float* bk   = (const float*)d_in[5];
    const float* Wv   = (const float*)d_in[6];
    const float* bv   = (const float*)d_in[7];
    const float* Wcq  = (const float*)d_in[8];
    const float* bcq  = (const float*)d_in[9];
    const float* Wck  = (const float*)d_in[10];
    const float* bck  = (const float*)d_in[11];
    const float* Wcv  = (const float*)d_in[12];
    const float* bcv  = (const float*)d_in[13];
    const float* g_q  = (const float*)d_in[14];
    const float* be_q = (const float*)d_in[15];
    const float* g_qc = (const float*)d_in[16];
    const float* be_qc= (const float*)d_in[17];
    const float* g_k  = (const float*)d_in[18];
    const float* be_k = (const float*)d_in[19];
    const float* g_kc = (const float*)d_in[20];
    const float* be_kc= (const float*)d_in[21];
    const float* g_v  = (const float*)d_in[22];
    const float* be_v = (const float*)d_in[23];
    const float* g_vc = (const float*)d_in[24];
    const float* be_vc= (const float*)d_in[25];
    const float* Wo   = (const float*)d_in[26];
    const float* bo   = (const float*)d_in[27];

    float* out  = (float*)d_out;
    float* attn = out + OUT_ELEMS;

    float *qb,*kb,*vbuf,*cx,*cadd;
    cudaGetSymbolAddress((void**)&qb,   d_qbuf);
    cudaGetSymbolAddress((void**)&kb,   d_kbuf);
    cudaGetSymbolAddress((void**)&vbuf, d_vbuf);
    cudaGetSymbolAddress((void**)&cx,   d_ctxbuf);
    cudaGetSymbolAddress((void**)&cadd, d_caddbuf);

    cproj_kernel<<<dim3(3,BB),256>>>(c, Wcq,bcq, Wck,bck, Wcv,bcv,
                                     g_qc,be_qc, g_kc,be_kc, g_vc,be_vc, cadd);

    dim3 gg(DD/128, MT/128);
    sgemm_bias<<<gg,256>>>(Q, Wq, bq, qb);
    sgemm_bias<<<gg,256>>>(Q, Wk, bk, kb);
    sgemm_bias<<<gg,256>>>(Q, Wv, bv, vbuf);

    lnadd_kernel<<<MT,256>>>(qb,   g_q, be_q, cadd + 0*BB*DD);
    lnadd_kernel<<<MT,256>>>(kb,   g_k, be_k, cadd + 1*BB*DD);
    lnadd_kernel<<<MT,256>>>(vbuf, g_v, be_v, cadd + 2*BB*DD);

    qk_kernel<<<dim3(SS/128, SS/128, BB*HH),256>>>(qb, kb, attn);
    softmax_kernel<<<BB*HH*SS,256>>>(attn);
    av_kernel<<<dim3(1, SS/128, BB*HH),256>>>(attn, vbuf, cx);

    sgemm_bias<<<gg,256>>>(cx, Wo, bo, out);
}

// round 5
// speedup vs baseline: 1.3289x; 1.3116x over previous
#include <cuda_runtime.h>
#include <cuda_bf16.h>
#include <math.h>
#include <stdint.h>

#define BB   8
#define SS   1024
#define DD   1024
#define HH   16
#define DKK  64
#define CFF  256
#define MT   (BB*SS)
#define OUT_ELEMS  (MT*DD)
#define SCALE_F 512.0f

typedef unsigned long long ull;

__device__ float d_qbuf[MT*DD];
__device__ float d_kbuf[MT*DD];
__device__ float d_vbuf[MT*DD];
__device__ float d_ctxbuf[MT*DD];
__device__ float d_caddbuf[3*BB*DD];
__device__ __nv_bfloat16 d_aplanes[(size_t)3*MT*DD];     // activation planes
__device__ __nv_bfloat16 d_wplanes[(size_t)4*3*DD*DD];   // 4 weights x 3 planes (transposed)

#define APL ((size_t)MT*DD)
#define WPL ((size_t)DD*DD)

// ---------------- helpers -------------------------------------------------------
__device__ __forceinline__ uint32_t smem_u32(const void* p){
    uint32_t a; asm("{.reg .u64 t; cvta.to.shared.u64 t, %1; cvt.u32.u64 %0, t;}":"=r"(a):"l"(p)); return a;
}
__device__ __forceinline__ ull pack2(float lo, float hi){
    ull r; asm("mov.b64 %0, {%1, %2};" : "=l"(r) : "f"(lo), "f"(hi)); return r;
}
__device__ __forceinline__ void fma2(ull& d, ull a, ull b){
    asm("fma.rn.f32x2 %0, %1, %2, %0;" : "+l"(d) : "l"(a), "l"(b));
}
__device__ __forceinline__ float2 unpack2(ull v){
    float2 r; asm("mov.b64 {%0, %1}, %2;" : "=f"(r.x), "=f"(r.y) : "l"(v)); return r;
}
__device__ __forceinline__ void ldsm_x4(uint32_t* r, uint32_t addr){
    asm volatile("ldmatrix.sync.aligned.m8n8.x4.shared.b16 {%0,%1,%2,%3}, [%4];"
        : "=r"(r[0]),"=r"(r[1]),"=r"(r[2]),"=r"(r[3]) : "r"(addr));
}
__device__ __forceinline__ void ldsm_x2(uint32_t* r, uint32_t addr){
    asm volatile("ldmatrix.sync.aligned.m8n8.x2.shared.b16 {%0,%1}, [%2];"
        : "=r"(r[0]),"=r"(r[1]) : "r"(addr));
}
__device__ __forceinline__ void mma16816(float* d, const uint32_t* a, const uint32_t* b){
    asm volatile("mma.sync.aligned.m16n8k16.row.col.f32.bf16.bf16.f32 "
        "{%0,%1,%2,%3}, {%4,%5,%6,%7}, {%8,%9}, {%0,%1,%2,%3};"
        : "+f"(d[0]),"+f"(d[1]),"+f"(d[2]),"+f"(d[3])
        : "r"(a[0]),"r"(a[1]),"r"(a[2]),"r"(a[3]), "r"(b[0]),"r"(b[1]));
}

// ---------------- bf16 3-way split ----------------------------------------------
__device__ __forceinline__ void split3(float a, __nv_bfloat16& h0, __nv_bfloat16& h1, __nv_bfloat16& h2){
    h0 = __float2bfloat16(a);
    float r = a - __bfloat162float(h0);
    h1 = __float2bfloat16(r);
    h2 = __float2bfloat16(r - __bfloat162float(h1));
}

__global__ void splitA_kernel(const float* __restrict__ X, __nv_bfloat16* __restrict__ P){
    size_t base = (size_t)blockIdx.x*DD;
    int t = threadIdx.x;
    float4 v = ((const float4*)(X+base))[t];
    __nv_bfloat16 a[3], b[3], c[3], d[3];
    split3(v.x,a[0],a[1],a[2]); split3(v.y,b[0],b[1],b[2]);
    split3(v.z,c[0],c[1],c[2]); split3(v.w,d[0],d[1],d[2]);
#pragma unroll
    for (int p=0;p<3;p++){
        __nv_bfloat162* dst = (__nv_bfloat162*)(P + p*APL + base + t*4);
        dst[0] = __nv_bfloat162(a[p], b[p]);
        dst[1] = __nv_bfloat162(c[p], d[p]);
    }
}

// weights: W[k][n] fp32 -> planes [n][k] bf16 (transposed)
__global__ void splitWT_kernel(const float* __restrict__ W, __nv_bfloat16* __restrict__ P){
    __shared__ float tile[32][33];
    int n0 = blockIdx.x*32, k0 = blockIdx.y*32;
    int tx = threadIdx.x&31, ty = threadIdx.x>>5;
#pragma unroll
    for (int i=0;i<32;i+=8)
        tile[ty+i][tx] = W[(size_t)(k0+ty+i)*DD + n0+tx];
    __syncthreads();
#pragma unroll
    for (int i=0;i<32;i+=8){
        float a = tile[tx][ty+i];
        __nv_bfloat16 h0,h1,h2; split3(a,h0,h1,h2);
        size_t o = (size_t)(n0+ty+i)*DD + k0+tx;
        P[0*WPL+o]=h0; P[1*WPL+o]=h1; P[2*WPL+o]=h2;
    }
}

// ---------- split-bf16 mma.sync GEMM: C = A @ W^T + bias --------------------------
// block 128x128, 8 warps (64x32 tiles), K-chunks 64, smem rows 144B
#define STRB  144
#define PLSZ  (128*STRB)     // 18432 B per plane tile
#define GEMM_SMEM_MAX (6*PLSZ)

__global__ void __launch_bounds__(256) gemm_mma(
    const __nv_bfloat16* __restrict__ Apl, const __nv_bfloat16* __restrict__ Bpl,
    const float* __restrict__ bias, float* __restrict__ C, int npairs)
{
    extern __shared__ char smc[];
    const int pc = (npairs==6)?3:2;
    int t=threadIdx.x, lane=t&31, wid=t>>5;
    int m0=blockIdx.y*128, n0=blockIdx.x*128;
    int wm=(wid>>2)*64, wn=(wid&3)*32;
    uint32_t sb = smem_u32(smc);

    float acc[16][4];
#pragma unroll
    for (int i=0;i<16;i++)
#pragma unroll
        for (int j=0;j<4;j++) acc[i][j]=0.f;

    const int P6A[6]={0,0,1,0,2,1}, P6B[6]={0,1,0,2,0,1};

    for (int ch=0; ch<16; ch++){
        int kc = ch*64;
        for (int p=0;p<pc;p++){
            const __nv_bfloat16* As  = Apl + (size_t)p*APL + (size_t)m0*DD + kc;
            const __nv_bfloat16* Bs2 = Bpl + (size_t)p*WPL + (size_t)n0*DD + kc;
            char* da = smc + p*PLSZ;
            char* db = smc + (pc+p)*PLSZ;
#pragma unroll
            for (int i=0;i<8;i++){
                int idx=t+i*256, r=idx>>4, c4=(idx&15)*4;
                uint2 va = *(const uint2*)(As  + (size_t)r*DD + c4);
                *(uint2*)(da + r*STRB + c4*2) = va;
                uint2 vb = *(const uint2*)(Bs2 + (size_t)r*DD + c4);
                *(uint2*)(db + r*STRB + c4*2) = vb;
            }
        }
        __syncthreads();
        for (int q=0;q<npairs;q++){
            uint32_t Abase = sb + P6A[q]*PLSZ;
            uint32_t Bbase = sb + (pc+P6B[q])*PLSZ;
#pragma unroll
            for (int ks=0;ks<4;ks++){
                uint32_t ar[4][4], br[4][2];
#pragma unroll
                for (int mt=0;mt<4;mt++)
                    ldsm_x4(ar[mt], Abase + (wm+mt*16+(lane&15))*STRB + ks*32 + (lane>>4)*16);
#pragma unroll
                for (int nt=0;nt<4;nt++)
                    ldsm_x2(br[nt], Bbase + (wn+nt*8+(lane&7))*STRB + ks*32 + ((lane>>3)&1)*16);
#pragma unroll
                for (int mt=0;mt<4;mt++)
#pragma unroll
                    for (int nt=0;nt<4;nt++)
                        mma16816(acc[mt*4+nt], ar[mt], br[nt]);
            }
        }
        __syncthreads();
    }

    int tr = lane>>2, tc = (lane&3)*2;
#pragma unroll
    for (int mt=0;mt<4;mt++)
#pragma unroll
        for (int nt=0;nt<4;nt++){
            int m = m0+wm+mt*16+tr, n = n0+wn+nt*8+tc;
            float b0 = bias[n], b1 = bias[n+1];
            float* c0 = C + (size_t)m*DD + n;
            float* c1 = C + (size_t)(m+8)*DD + n;
            c0[0]=acc[mt*4+nt][0]+b0; c0[1]=acc[mt*4+nt][1]+b1;
            c1[0]=acc[mt*4+nt][2]+b0; c1[1]=acc[mt*4+nt][3]+b1;
        }
}

// ---------------- small c-branch -------------------------------------------------
__global__ void cproj_kernel(const float* __restrict__ c,
    const float* __restrict__ Wcq, const float* __restrict__ bcq,
    const float* __restrict__ Wck, const float* __restrict__ bck,
    const float* __restrict__ Wcv, const float* __restrict__ bcv,
    const float* __restrict__ gqc, const float* __restrict__ beqc,
    const float* __restrict__ gkc, const float* __restrict__ bekc,
    const float* __restrict__ gvc, const float* __restrict__ bevc,
    float* __restrict__ cadd)
{
    int p = blockIdx.x, b = blockIdx.y, t = threadIdx.x;
    const float* W  = (p==0)?Wcq:((p==1)?Wck:Wcv);
    const float* bi = (p==0)?bcq:((p==1)?bck:bcv);
    const float* g  = (p==0)?gqc:((p==1)?gkc:gvc);
    const float* be = (p==0)?beqc:((p==1)?bekc:bevc);
    __shared__ float sc[CFF];
    __shared__ float red[256];
    sc[t] = c[b*CFF + t];
    __syncthreads();
    float y[4];
#pragma unroll
    for (int jj=0;jj<4;jj++){
        int j = jj*256 + t;
        float acc = bi[j];
        for (int i=0;i<CFF;i++) acc += sc[i]*W[(size_t)i*DD + j];
        y[jj]=acc;
    }
    float s=(y[0]+y[1])+(y[2]+y[3]);
    red[t]=s; __syncthreads();
    for (int st=128;st>0;st>>=1){ if(t<st) red[t]+=red[t+st]; __syncthreads(); }
    float mu = red[0]*(1.0f/DD);
    __syncthreads();
    float vv=0.f;
#pragma unroll
    for (int jj=0;jj<4;jj++){ float d0=y[jj]-mu; vv += d0*d0; }
    red[t]=vv; __syncthreads();
    for (int st=128;st>0;st>>=1){ if(t<st) red[t]+=red[t+st]; __syncthreads(); }
    float rs = 1.0f/sqrtf(red[0]*(1.0f/DD) + 1e-5f);
#pragma unroll
    for (int jj=0;jj<4;jj++){
        int j = jj*256 + t;
        cadd[(size_t)(p*BB + b)*DD + j] = (y[jj]-mu)*rs*g[j] + be[j];
    }
}

// ---------------- LN + broadcast add ----------------------------------------------
__global__ void lnadd_kernel(float* __restrict__ buf,
    const float* __restrict__ g, const float* __restrict__ be,
    const float* __restrict__ cadd)
{
    __shared__ float red[256];
    int t = threadIdx.x, r = blockIdx.x;
    float4* row = (float4*)(buf + (size_t)r*DD);
    float4 v = row[t];
    red[t]=(v.x+v.y)+(v.z+v.w); __syncthreads();
    for (int st=128;st>0;st>>=1){ if(t<st) red[t]+=red[t+st]; __syncthreads(); }
    float mu = red[0]*(1.0f/DD);
    __syncthreads();
    float dx=v.x-mu, dy=v.y-mu, dz=v.z-mu, dw=v.w-mu;
    red[t]=(dx*dx+dy*dy)+(dz*dz+dw*dw); __syncthreads();
    for (int st=128;st>0;st>>=1){ if(t<st) red[t]+=red[t+st]; __syncthreads(); }
    float rs = 1.0f/sqrtf(red[0]*(1.0f/DD) + 1e-5f);
    float4 gg=((const float4*)g)[t], bb=((const float4*)be)[t];
    float4 cc=((const float4*)(cadd+(size_t)(r>>10)*DD))[t];
    float4 o = {dx*rs*gg.x+bb.x+cc.x, dy*rs*gg.y+bb.y+cc.y,
                dz*rs*gg.z+bb.z+cc.z, dw*rs*gg.w+bb.w+cc.w};
    row[t]=o;
}

// ---------------- QK^T (scalar fp32, FFMA2) ----------------------------------------
__global__ void __launch_bounds__(256) qk_kernel(
    const float* __restrict__ qb, const float* __restrict__ kb,
    float* __restrict__ attn)
{
    __shared__ float Qs[32][128];
    __shared__ float Ks[32][128];
    int t = threadIdx.x, bh = blockIdx.z;
    const float* qbase = qb + (size_t)(bh>>4)*SS*DD + (bh&15)*DKK;
    const float* kbase = kb + (size_t)(bh>>4)*SS*DD + (bh&15)*DKK;
    float* obase = attn + (size_t)bh*SS*SS;
    int m0 = blockIdx.y*128, n0 = blockIdx.x*128;
    int ty=t>>4, tx=t&15, row=t&127, half=t>>7;

    ull acc[8][4];
#pragma unroll
    for (int r=0;r<8;r++)
#pragma unroll
        for (int g=0;g<4;g++) acc[r][g]=0ULL;

    for (int kk=0; kk<DKK; kk+=32){
#pragma unroll
        for (int i=0;i<4;i++){
            int dd = half*16 + i*4;
            float4 qv = *(const float4*)(qbase + (size_t)(m0+row)*DD + kk + dd);
            Qs[dd+0][row]=qv.x; Qs[dd+1][row]=qv.y; Qs[dd+2][row]=qv.z; Qs[dd+3][row]=qv.w;
            float4 kv = *(const float4*)(kbase + (size_t)(n0+row)*DD + kk + dd);
            Ks[dd+0][row]=kv.x; Ks[dd+1][row]=kv.y; Ks[dd+2][row]=kv.z; Ks[dd+3][row]=kv.w;
        }
        __syncthreads();
#pragma unroll
        for (int d=0; d<32; d++){
            float4 av0 = *(float4*)&Qs[d][ty*8];
            float4 av1 = *(float4*)&Qs[d][ty*8+4];
            ulonglong2 bl0 = *(ulonglong2*)&Ks[d][tx*8];
            ulonglong2 bl1 = *(ulonglong2*)&Ks[d][tx*8+4];
            ull aa[8];
            aa[0]=pack2(av0.x,av0.x); aa[1]=pack2(av0.y,av0.y);
            aa[2]=pack2(av0.z,av0.z); aa[3]=pack2(av0.w,av0.w);
            aa[4]=pack2(av1.x,av1.x); aa[5]=pack2(av1.y,av1.y);
            aa[6]=pack2(av1.z,av1.z); aa[7]=pack2(av1.w,av1.w);
#pragma unroll
            for (int r=0;r<8;r++){
                fma2(acc[r][0],aa[r],bl0.x);
                fma2(acc[r][1],aa[r],bl0.y);
                fma2(acc[r][2],aa[r],bl1.x);
                fma2(acc[r][3],aa[r],bl1.y);
            }
        }
        __syncthreads();
    }
#pragma unroll
    for (int r=0;r<8;r++){
        float2 u0=unpack2(acc[r][0]), u1=unpack2(acc[r][1]);
        float2 u2=unpack2(acc[r][2]), u3=unpack2(acc[r][3]);
        size_t o = (size_t)(m0+ty*8+r)*SS + n0 + tx*8;
        float4 o0={u0.x*SCALE_F,u0.y*SCALE_F,u1.x*SCALE_F,u1.y*SCALE_F};
        float4 o1={u2.x*SCALE_F,u2.y*SCALE_F,u3.x*SCALE_F,u3.y*SCALE_F};
        *(float4*)(obase+o)=o0; *(float4*)(obase+o+4)=o1;
    }
}

// ---------------- softmax -----------------------------------------------------------
__global__ void softmax_kernel(float* __restrict__ attn)
{
    __shared__ float red[256];
    int t = threadIdx.x;
    float4* p = (float4*)(attn + (size_t)blockIdx.x*SS);
    float4 v = p[t];
    float m = fmaxf(fmaxf(v.x,v.y), fmaxf(v.z,v.w));
    red[t]=m; __syncthreads();
    for (int st=128;st>0;st>>=1){ if(t<st) red[t]=fmaxf(red[t],red[t+st]); __syncthreads(); }
    m = red[0]; __syncthreads();
    float4 e = {expf(v.x-m), expf(v.y-m), expf(v.z-m), expf(v.w-m)};
    red[t]=(e.x+e.y)+(e.z+e.w); __syncthreads();
    for (int st=128;st>0;st>>=1){ if(t<st) red[t]+=red[t+st]; __syncthreads(); }
    float inv = 1.0f/red[0];
    e.x*=inv; e.y*=inv; e.z*=inv; e.w*=inv;
    p[t]=e;
}

// ---------------- attn @ V (scalar fp32, FFMA2) -------------------------------------
__global__ void __launch_bounds__(256) av_kernel(
    const float* __restrict__ attn, const float* __restrict__ vb,
    float* __restrict__ cx)
{
    __shared__ float Ps[32][128];
    __shared__ float Vs[32][64];
    int t = threadIdx.x, bh = blockIdx.z;
    const float* pbase = attn + (size_t)bh*SS*SS;
    const float* vbase = vb + (size_t)(bh>>4)*SS*DD + (bh&15)*DKK;
    float* obase = cx + (size_t)(bh>>4)*SS*DD + (bh&15)*DKK;
    int m0 = blockIdx.y*128;
    int ty=t>>4, tx=t&15, row=t&127, half=t>>7;
    int vkr=t>>4, vnc=(t&15)*4;

    ull acc[8][2];
#pragma unroll
    for (int r=0;r<8;r++){ acc[r][0]=0ULL; acc[r][1]=0ULL; }

    for (int k0=0;k0<SS;k0+=32){
#pragma unroll
        for (int i=0;i<4;i++){
            int kq = half*16 + i*4;
            float4 pv = *(const float4*)(pbase + (size_t)(m0+row)*SS + k0 + kq);
            Ps[kq+0][row]=pv.x; Ps[kq+1][row]=pv.y; Ps[kq+2][row]=pv.z; Ps[kq+3][row]=pv.w;
        }
        float4 v0 = *(const float4*)(vbase + (size_t)(k0+vkr   )*DD + vnc);
        float4 v1 = *(const float4*)(vbase + (size_t)(k0+vkr+16)*DD + vnc);
        *(float4*)&Vs[vkr   ][vnc]=v0;
        *(float4*)&Vs[vkr+16][vnc]=v1;
        __syncthreads();
#pragma unroll
        for (int kk=0; kk<32; kk++){
            float4 av0 = *(float4*)&Ps[kk][ty*8];
            float4 av1 = *(float4*)&Ps[kk][ty*8+4];
            ulonglong2 bv = *(ulonglong2*)&Vs[kk][tx*4];
            ull aa[8];
            aa[0]=pack2(av0.x,av0.x); aa[1]=pack2(av0.y,av0.y);
            aa[2]=pack2(av0.z,av0.z); aa[3]=pack2(av0.w,av0.w);
            aa[4]=pack2(av1.x,av1.x); aa[5]=pack2(av1.y,av1.y);
            aa[6]=pack2(av1.z,av1.z); aa[7]=pack2(av1.w,av1.w);
#pragma unroll
            for (int r=0;r<8;r++){
                fma2(acc[r][0],aa[r],bv.x);
                fma2(acc[r][1],aa[r],bv.y);
            }
        }
        __syncthreads();
    }
#pragma unroll
    for (int r=0;r<8;r++){
        float2 u0=unpack2(acc[r][0]), u1=unpack2(acc[r][1]);
        float4 o = {u0.x,u0.y,u1.x,u1.y};
        *(float4*)(obase + (size_t)(m0+ty*8+r)*DD + tx*4) = o;
    }
}

// ------------------------------- launch ---------------------------------------------
extern "C" void kernel_launch(void* const* d_in, const int* in_sizes, int n_in,
                              void* d_out, int out_size)
{
    const float* Q    = (const float*)d_in[0];
    const float* c    = (const float*)d_in[1];
    const float* Wq   = (const float*)d_in[2];
    const float* bq   = (const float*)d_in[3];
    const float* Wk   = (const float*)d_in[4];
    const float* bk   = (const float*)d_in[5];
    const float* Wv   = (const float*)d_in[6];
    const float* bv   = (const float*)d_in[7];
    const float* Wcq  = (const float*)d_in[8];
    const float* bcq  = (const float*)d_in[9];
    const float* Wck  = (const float*)d_in[10];
    const float* bck  = (const float*)d_in[11];
    const float* Wcv  = (const float*)d_in[12];
    const float* bcv  = (const float*)d_in[13];
    const float* g_q  = (const float*)d_in[14];
    const float* be_q = (const float*)d_in[15];
    const float* g_qc = (const float*)d_in[16];
    const float* be_qc= (const float*)d_in[17];
    const float* g_k  = (const float*)d_in[18];
    const float* be_k = (const float*)d_in[19];
    const float* g_kc = (const float*)d_in[20];
    const float* be_kc= (const float*)d_in[21];
    const float* g_v  = (const float*)d_in[22];
    const float* be_v = (const float*)d_in[23];
    const float* g_vc = (const float*)d_in[24];
    const float* be_vc= (const float*)d_in[25];
    const float* Wo   = (const float*)d_in[26];
    const float* bo   = (const float*)d_in[27];

    float* out  = (float*)d_out;
    float* attn = out + OUT_ELEMS;

    float *qb,*kb,*vbuf,*cx,*cadd;
    __nv_bfloat16 *apl,*wpl;
    cudaGetSymbolAddress((void**)&qb,   d_qbuf);
    cudaGetSymbolAddress((void**)&kb,   d_kbuf);
    cudaGetSymbolAddress((void**)&vbuf, d_vbuf);
    cudaGetSymbolAddress((void**)&cx,   d_ctxbuf);
    cudaGetSymbolAddress((void**)&cadd, d_caddbuf);
    cudaGetSymbolAddress((void**)&apl,  d_aplanes);
    cudaGetSymbolAddress((void**)&wpl,  d_wplanes);

    cudaFuncSetAttribute(gemm_mma, cudaFuncAttributeMaxDynamicSharedMemorySize, GEMM_SMEM_MAX);

    cproj_kernel<<<dim3(3,BB),256>>>(c, Wcq,bcq, Wck,bck, Wcv,bcv,
                                     g_qc,be_qc, g_kc,be_kc, g_vc,be_vc, cadd);

    splitWT_kernel<<<dim3(32,32),256>>>(Wq, wpl + 0*3*WPL);
    splitWT_kernel<<<dim3(32,32),256>>>(Wk, wpl + 1*3*WPL);
    splitWT_kernel<<<dim3(32,32),256>>>(Wv, wpl + 2*3*WPL);
    splitWT_kernel<<<dim3(32,32),256>>>(Wo, wpl + 3*3*WPL);
    splitA_kernel<<<MT,256>>>(Q, apl);

    dim3 gg(DD/128, MT/128);
    gemm_mma<<<gg,256,6*PLSZ>>>(apl, wpl + 0*3*WPL, bq, qb,   6);
    gemm_mma<<<gg,256,6*PLSZ>>>(apl, wpl + 1*3*WPL, bk, kb,   6);
    gemm_mma<<<gg,256,4*PLSZ>>>(apl, wpl + 2*3*WPL, bv, vbuf, 3);

    lnadd_kernel<<<MT,256>>>(qb,   g_q, be_q, cadd + 0*BB*DD);
    lnadd_kernel<<<MT,256>>>(kb,   g_k, be_k, cadd + 1*BB*DD);
    lnadd_kernel<<<MT,256>>>(vbuf, g_v, be_v, cadd + 2*BB*DD);

    qk_kernel<<<dim3(SS/128, SS/128, BB*HH),256>>>(qb, kb, attn);
    softmax_kernel<<<BB*HH*SS,256>>>(attn);
    av_kernel<<<dim3(1, SS/128, BB*HH),256>>>(attn, vbuf, cx);

    splitA_kernel<<<MT,256>>>(cx, apl);
    gemm_mma<<<gg,256,4*PLSZ>>>(apl, wpl + 3*3*WPL, bo, out, 3);
}

// round 6
// speedup vs baseline: 1.5085x; 1.1351x over previous
#include <cuda_runtime.h>
#include <cuda_bf16.h>
#include <math.h>
#include <stdint.h>

#define BB   8
#define SS   1024
#define DD   1024
#define HH   16
#define DKK  64
#define CFF  256
#define MT   (BB*SS)
#define OUT_ELEMS  (MT*DD)
#define SCALE_F 512.0f

typedef unsigned long long ull;

__device__ float d_qbuf[MT*DD];
__device__ float d_kbuf[MT*DD];
__device__ float d_vbuf[MT*DD];
__device__ float d_ctxbuf[MT*DD];
__device__ float d_caddbuf[3*BB*DD];
__device__ __nv_bfloat16 d_aplanes[(size_t)3*MT*DD];     // activation planes (A of gemm / q planes)
__device__ __nv_bfloat16 d_kplanes[(size_t)3*MT*DD];     // k planes
__device__ __nv_bfloat16 d_wplanes[(size_t)4*3*DD*DD];   // 4 weights x 3 planes (transposed)
__device__ __nv_bfloat16 d_pplanes[(size_t)2*BB*HH*SS*SS]; // attn prob planes
__device__ __nv_bfloat16 d_vtpl[(size_t)2*BB*HH*DKK*SS];   // V^T planes per head

#define APL ((size_t)MT*DD)
#define WPL ((size_t)DD*DD)
#define PPL ((size_t)BB*HH*SS*SS)
#define VTPL ((size_t)BB*HH*DKK*SS)

// ---------------- helpers -------------------------------------------------------
__device__ __forceinline__ uint32_t smem_u32(const void* p){
    uint32_t a; asm("{.reg .u64 t; cvta.to.shared.u64 t, %1; cvt.u32.u64 %0, t;}":"=r"(a):"l"(p)); return a;
}
__device__ __forceinline__ void ldsm_x4(uint32_t* r, uint32_t addr){
    asm volatile("ldmatrix.sync.aligned.m8n8.x4.shared.b16 {%0,%1,%2,%3}, [%4];"
        : "=r"(r[0]),"=r"(r[1]),"=r"(r[2]),"=r"(r[3]) : "r"(addr));
}
__device__ __forceinline__ void ldsm_x2(uint32_t* r, uint32_t addr){
    asm volatile("ldmatrix.sync.aligned.m8n8.x2.shared.b16 {%0,%1}, [%2];"
        : "=r"(r[0]),"=r"(r[1]) : "r"(addr));
}
__device__ __forceinline__ void mma16816(float* d, const uint32_t* a, const uint32_t* b){
    asm volatile("mma.sync.aligned.m16n8k16.row.col.f32.bf16.bf16.f32 "
        "{%0,%1,%2,%3}, {%4,%5,%6,%7}, {%8,%9}, {%0,%1,%2,%3};"
        : "+f"(d[0]),"+f"(d[1]),"+f"(d[2]),"+f"(d[3])
        : "r"(a[0]),"r"(a[1]),"r"(a[2]),"r"(a[3]), "r"(b[0]),"r"(b[1]));
}
__device__ __forceinline__ void split3(float a, __nv_bfloat16& h0, __nv_bfloat16& h1, __nv_bfloat16& h2){
    h0 = __float2bfloat16(a);
    float r = a - __bfloat162float(h0);
    h1 = __float2bfloat16(r);
    h2 = __float2bfloat16(r - __bfloat162float(h1));
}

__global__ void splitA_kernel(const float* __restrict__ X, __nv_bfloat16* __restrict__ P){
    size_t base = (size_t)blockIdx.x*DD;
    int t = threadIdx.x;
    float4 v = ((const float4*)(X+base))[t];
    __nv_bfloat16 a[3], b[3], c[3], d[3];
    split3(v.x,a[0],a[1],a[2]); split3(v.y,b[0],b[1],b[2]);
    split3(v.z,c[0],c[1],c[2]); split3(v.w,d[0],d[1],d[2]);
#pragma unroll
    for (int p=0;p<3;p++){
        __nv_bfloat162* dst = (__nv_bfloat162*)(P + p*APL + base + t*4);
        dst[0] = __nv_bfloat162(a[p], b[p]);
        dst[1] = __nv_bfloat162(c[p], d[p]);
    }
}

// weights: W[k][n] fp32 -> planes [n][k] bf16 (transposed)
__global__ void splitWT_kernel(const float* __restrict__ W, __nv_bfloat16* __restrict__ P){
    __shared__ float tile[32][33];
    int n0 = blockIdx.x*32, k0 = blockIdx.y*32;
    int tx = threadIdx.x&31, ty = threadIdx.x>>5;
#pragma unroll
    for (int i=0;i<32;i+=8)
        tile[ty+i][tx] = W[(size_t)(k0+ty+i)*DD + n0+tx];
    __syncthreads();
#pragma unroll
    for (int i=0;i<32;i+=8){
        float a = tile[tx][ty+i];
        __nv_bfloat16 h0,h1,h2; split3(a,h0,h1,h2);
        size_t o = (size_t)(n0+ty+i)*DD + k0+tx;
        P[0*WPL+o]=h0; P[1*WPL+o]=h1; P[2*WPL+o]=h2;
    }
}

// V^T per head, 2-term split: vbuf[(b,s)][h*64+d] -> vt[p][bh][d][s]
__global__ void vtrans_kernel(const float* __restrict__ vb, __nv_bfloat16* __restrict__ vt){
    __shared__ float tile[32][33];
    int dt = blockIdx.x, s0 = blockIdx.y*32, bh = blockIdx.z;
    int b = bh>>4, h = bh&15, d0 = dt*32;
    int t = threadIdx.x;
    int sr = t>>3, dc = (t&7)*4;
    float4 v = *(const float4*)(vb + (size_t)(b*SS + s0+sr)*DD + h*DKK + d0 + dc);
    tile[sr][dc]=v.x; tile[sr][dc+1]=v.y; tile[sr][dc+2]=v.z; tile[sr][dc+3]=v.w;
    __syncthreads();
    int dr = t>>3, sc = (t&7)*4;
    __nv_bfloat16 o0[4], o1[4];
#pragma unroll
    for (int j=0;j<4;j++){
        float val = tile[sc+j][dr];
        o0[j] = __float2bfloat16(val);
        o1[j] = __float2bfloat16(val - __bfloat162float(o0[j]));
    }
    size_t dst = (size_t)bh*DKK*SS + (size_t)(d0+dr)*SS + s0+sc;
    *(uint2*)(vt + dst)        = *(uint2*)o0;
    *(uint2*)(vt + VTPL + dst) = *(uint2*)o1;
}

// ---------- split-bf16 mma.sync GEMM: C = A @ W^T + bias (unchanged, proven) -----
#define STRB  144
#define PLSZ  (128*STRB)
#define GEMM_SMEM_MAX (6*PLSZ)

__global__ void __launch_bounds__(256) gemm_mma(
    const __nv_bfloat16* __restrict__ Apl, const __nv_bfloat16* __restrict__ Bpl,
    const float* __restrict__ bias, float* __restrict__ C, int npairs)
{
    extern __shared__ char smc[];
    const int pc = (npairs==6)?3:2;
    int t=threadIdx.x, lane=t&31, wid=t>>5;
    int m0=blockIdx.y*128, n0=blockIdx.x*128;
    int wm=(wid>>2)*64, wn=(wid&3)*32;
    uint32_t sb = smem_u32(smc);

    float acc[16][4];
#pragma unroll
    for (int i=0;i<16;i++)
#pragma unroll
        for (int j=0;j<4;j++) acc[i][j]=0.f;

    const int P6A[6]={0,0,1,0,2,1}, P6B[6]={0,1,0,2,0,1};

    for (int ch=0; ch<16; ch++){
        int kc = ch*64;
        for (int p=0;p<pc;p++){
            const __nv_bfloat16* As  = Apl + (size_t)p*APL + (size_t)m0*DD + kc;
            const __nv_bfloat16* Bs2 = Bpl + (size_t)p*WPL + (size_t)n0*DD + kc;
            char* da = smc + p*PLSZ;
            char* db = smc + (pc+p)*PLSZ;
#pragma unroll
            for (int i=0;i<8;i++){
                int idx=t+i*256, r=idx>>4, c4=(idx&15)*4;
                uint2 va = *(const uint2*)(As  + (size_t)r*DD + c4);
                *(uint2*)(da + r*STRB + c4*2) = va;
                uint2 vb = *(const uint2*)(Bs2 + (size_t)r*DD + c4);
                *(uint2*)(db + r*STRB + c4*2) = vb;
            }
        }
        __syncthreads();
        for (int q=0;q<npairs;q++){
            uint32_t Abase = sb + P6A[q]*PLSZ;
            uint32_t Bbase = sb + (pc+P6B[q])*PLSZ;
#pragma unroll
            for (int ks=0;ks<4;ks++){
                uint32_t ar[4][4], br[4][2];
#pragma unroll
                for (int mt=0;mt<4;mt++)
                    ldsm_x4(ar[mt], Abase + (wm+mt*16+(lane&15))*STRB + ks*32 + (lane>>4)*16);
#pragma unroll
                for (int nt=0;nt<4;nt++)
                    ldsm_x2(br[nt], Bbase + (wn+nt*8+(lane&7))*STRB + ks*32 + ((lane>>3)&1)*16);
#pragma unroll
                for (int mt=0;mt<4;mt++)
#pragma unroll
                    for (int nt=0;nt<4;nt++)
                        mma16816(acc[mt*4+nt], ar[mt], br[nt]);
            }
        }
        __syncthreads();
    }

    int tr = lane>>2, tc = (lane&3)*2;
#pragma unroll
    for (int mt=0;mt<4;mt++)
#pragma unroll
        for (int nt=0;nt<4;nt++){
            int m = m0+wm+mt*16+tr, n = n0+wn+nt*8+tc;
            float b0 = bias[n], b1 = bias[n+1];
            float* c0 = C + (size_t)m*DD + n;
            float* c1 = C + (size_t)(m+8)*DD + n;
            c0[0]=acc[mt*4+nt][0]+b0; c0[1]=acc[mt*4+nt][1]+b1;
            c1[0]=acc[mt*4+nt][2]+b0; c1[1]=acc[mt*4+nt][3]+b1;
        }
}

// ---------- qk mma: attn_raw = (q4 k4^T)*512, 3-term split (6 pairs) -------------
// tiles per (b,h): 128x128, K=64, XOR-swizzled 128B smem rows
#define QKPL 16384
__global__ void __launch_bounds__(256) qk_mma(
    const __nv_bfloat16* __restrict__ qpl, const __nv_bfloat16* __restrict__ kpl,
    float* __restrict__ attn)
{
    extern __shared__ char smc[];
    int t=threadIdx.x, lane=t&31, wid=t>>5;
    int bh = blockIdx.z, b = bh>>4, h = bh&15;
    int m0 = blockIdx.y*128, n0 = blockIdx.x*128;
    int wm=(wid>>2)*64, wn=(wid&3)*32;
    uint32_t sb = smem_u32(smc);

    // load 3 q planes + 3 k planes (128 rows x 64 cols each)
#pragma unroll
    for (int p=0;p<3;p++){
        const __nv_bfloat16* qs = qpl + (size_t)p*APL + (size_t)(b*SS+m0)*DD + h*DKK;
        const __nv_bfloat16* ks2= kpl + (size_t)p*APL + (size_t)(b*SS+n0)*DD + h*DKK;
        char* da = smc + p*QKPL;
        char* db = smc + (3+p)*QKPL;
#pragma unroll
        for (int i=0;i<8;i++){
            int u = t + i*256;          // 0..2047
            int r = u>>4, sub = u&15;   // sub: 8B unit
            int u16 = sub>>1, in8 = (sub&1)*8;
            uint32_t off = r*128 + (((u16) ^ (r&7))<<4) + in8;
            *(uint2*)(da + off) = *(const uint2*)(qs + (size_t)r*DD + sub*4);
            *(uint2*)(db + off) = *(const uint2*)(ks2 + (size_t)r*DD + sub*4);
        }
    }
    __syncthreads();

    float acc[16][4];
#pragma unroll
    for (int i=0;i<16;i++)
#pragma unroll
        for (int j=0;j<4;j++) acc[i][j]=0.f;

    const int P6A[6]={0,0,1,0,2,1}, P6B[6]={0,1,0,2,0,1};
    for (int q=0;q<6;q++){
        uint32_t Abase = sb + P6A[q]*QKPL;
        uint32_t Bbase = sb + (3+P6B[q])*QKPL;
#pragma unroll
        for (int ks=0;ks<4;ks++){
            uint32_t ar[4][4], br[4][2];
#pragma unroll
            for (int mt=0;mt<4;mt++){
                int r = wm+mt*16+(lane&15);
                int u16 = ks*2 + (lane>>4);
                ldsm_x4(ar[mt], Abase + r*128 + ((u16 ^ (r&7))<<4));
            }
#pragma unroll
            for (int nt=0;nt<4;nt++){
                int r = wn+nt*8+(lane&7);
                int u16 = ks*2 + ((lane>>3)&1);
                ldsm_x2(br[nt], Bbase + r*128 + ((u16 ^ (r&7))<<4));
            }
#pragma unroll
            for (int mt=0;mt<4;mt++)
#pragma unroll
                for (int nt=0;nt<4;nt++)
                    mma16816(acc[mt*4+nt], ar[mt], br[nt]);
        }
    }

    float* obase = attn + (size_t)bh*SS*SS;
    int tr = lane>>2, tc = (lane&3)*2;
#pragma unroll
    for (int mt=0;mt<4;mt++)
#pragma unroll
        for (int nt=0;nt<4;nt++){
            int m = m0+wm+mt*16+tr, n = n0+wn+nt*8+tc;
            float* c0 = obase + (size_t)m*SS + n;
            float* c1 = obase + (size_t)(m+8)*SS + n;
            c0[0]=acc[mt*4+nt][0]*SCALE_F; c0[1]=acc[mt*4+nt][1]*SCALE_F;
            c1[0]=acc[mt*4+nt][2]*SCALE_F; c1[1]=acc[mt*4+nt][3]*SCALE_F;
        }
}

// ---------- softmax + 2-term P-plane split ---------------------------------------
__global__ void softmax_kernel(float* __restrict__ attn,
    __nv_bfloat16* __restrict__ pp)
{
    __shared__ float red[256];
    int t = threadIdx.x;
    size_t row = blockIdx.x;
    float4* p = (float4*)(attn + row*SS);
    float4 v = p[t];
    float m = fmaxf(fmaxf(v.x,v.y), fmaxf(v.z,v.w));
    red[t]=m; __syncthreads();
    for (int st=128;st>0;st>>=1){ if(t<st) red[t]=fmaxf(red[t],red[t+st]); __syncthreads(); }
    m = red[0]; __syncthreads();
    float4 e = {expf(v.x-m), expf(v.y-m), expf(v.z-m), expf(v.w-m)};
    red[t]=(e.x+e.y)+(e.z+e.w); __syncthreads();
    for (int st=128;st>0;st>>=1){ if(t<st) red[t]+=red[t+st]; __syncthreads(); }
    float inv = 1.0f/red[0];
    e.x*=inv; e.y*=inv; e.z*=inv; e.w*=inv;
    p[t]=e;
    __nv_bfloat16 o0[4], o1[4];
    float ev[4] = {e.x,e.y,e.z,e.w};
#pragma unroll
    for (int j=0;j<4;j++){
        o0[j] = __float2bfloat16(ev[j]);
        o1[j] = __float2bfloat16(ev[j] - __bfloat162float(o0[j]));
    }
    size_t dst = row*SS + t*4;
    *(uint2*)(pp + dst)       = *(uint2*)o0;
    *(uint2*)(pp + PPL + dst) = *(uint2*)o1;
}

// ---------- av mma: ctx = P @ V, 2-term split (3 pairs) ---------------------------
// per (bh, mtile): 128x64 tile, K=1024 in 64-chunks
#define AVA 16384
#define AVB 8192
__global__ void __launch_bounds__(256) av_mma(
    const __nv_bfloat16* __restrict__ pp, const __nv_bfloat16* __restrict__ vt,
    float* __restrict__ cx)
{
    extern __shared__ char smc[];
    int t=threadIdx.x, lane=t&31, wid=t>>5;
    int m0 = blockIdx.x*128, bh = blockIdx.y;
    int b = bh>>4, h = bh&15;
    int wm=(wid>>1)*32, wn=(wid&1)*32;
    uint32_t sb = smem_u32(smc);

    float acc[8][4];
#pragma unroll
    for (int i=0;i<8;i++)
#pragma unroll
        for (int j=0;j<4;j++) acc[i][j]=0.f;

    const int P2A[3]={0,0,1}, P2B[3]={0,1,0};

    for (int ch=0; ch<16; ch++){
        int kc = ch*64;
#pragma unroll
        for (int p=0;p<2;p++){
            const __nv_bfloat16* as = pp + (size_t)p*PPL + (size_t)bh*SS*SS + (size_t)m0*SS + kc;
            char* da = smc + p*AVA;
#pragma unroll
            for (int i=0;i<8;i++){
                int u = t + i*256;
                int r = u>>4, sub = u&15;
                uint32_t off = r*128 + ((((sub>>1)) ^ (r&7))<<4) + (sub&1)*8;
                *(uint2*)(da + off) = *(const uint2*)(as + (size_t)r*SS + sub*4);
            }
            const __nv_bfloat16* bs = vt + (size_t)p*VTPL + (size_t)bh*DKK*SS + kc;
            char* db = smc + 2*AVA + p*AVB;
#pragma unroll
            for (int i=0;i<4;i++){
                int u = t + i*256;      // 0..1023, 64 rows x 16 subs
                int r = u>>4, sub = u&15;
                uint32_t off = r*128 + ((((sub>>1)) ^ (r&7))<<4) + (sub&1)*8;
                *(uint2*)(db + off) = *(const uint2*)(bs + (size_t)r*SS + sub*4);
            }
        }
        __syncthreads();
        for (int q=0;q<3;q++){
            uint32_t Abase = sb + P2A[q]*AVA;
            uint32_t Bbase = sb + 2*AVA + P2B[q]*AVB;
#pragma unroll
            for (int ks=0;ks<4;ks++){
                uint32_t ar[2][4], br[4][2];
#pragma unroll
                for (int mt=0;mt<2;mt++){
                    int r = wm+mt*16+(lane&15);
                    int u16 = ks*2 + (lane>>4);
                    ldsm_x4(ar[mt], Abase + r*128 + ((u16 ^ (r&7))<<4));
                }
#pragma unroll
                for (int nt=0;nt<4;nt++){
                    int r = wn+nt*8+(lane&7);
                    int u16 = ks*2 + ((lane>>3)&1);
                    ldsm_x2(br[nt], Bbase + r*128 + ((u16 ^ (r&7))<<4));
                }
#pragma unroll
                for (int mt=0;mt<2;mt++)
#pragma unroll
                    for (int nt=0;nt<4;nt++)
                        mma16816(acc[mt*4+nt], ar[mt], br[nt]);
            }
        }
        __syncthreads();
    }

    int tr = lane>>2, tc = (lane&3)*2;
#pragma unroll
    for (int mt=0;mt<2;mt++)
#pragma unroll
        for (int nt=0;nt<4;nt++){
            int m = b*SS + m0 + wm + mt*16 + tr;
            int n = h*DKK + wn + nt*8 + tc;
            float* c0 = cx + (size_t)m*DD + n;
            float* c1 = cx + (size_t)(m+8)*DD + n;
            c0[0]=acc[mt*4+nt][0]; c0[1]=acc[mt*4+nt][1];
            c1[0]=acc[mt*4+nt][2]; c1[1]=acc[mt*4+nt][3];
        }
}

// ---------------- small c-branch -------------------------------------------------
__global__ void cproj_kernel(const float* __restrict__ c,
    const float* __restrict__ Wcq, const float* __restrict__ bcq,
    const float* __restrict__ Wck, const float* __restrict__ bck,
    const float* __restrict__ Wcv, const float* __restrict__ bcv,
    const float* __restrict__ gqc, const float* __restrict__ beqc,
    const float* __restrict__ gkc, const float* __restrict__ bekc,
    const float* __restrict__ gvc, const float* __restrict__ bevc,
    float* __restrict__ cadd)
{
    int p = blockIdx.x, b = blockIdx.y, t = threadIdx.x;
    const float* W  = (p==0)?Wcq:((p==1)?Wck:Wcv);
    const float* bi = (p==0)?bcq:((p==1)?bck:bcv);
    const float* g  = (p==0)?gqc:((p==1)?gkc:gvc);
    const float* be = (p==0)?beqc:((p==1)?bekc:bevc);
    __shared__ float sc[CFF];
    __shared__ float red[256];
    sc[t] = c[b*CFF + t];
    __syncthreads();
    float y[4];
#pragma unroll
    for (int jj=0;jj<4;jj++){
        int j = jj*256 + t;
        float acc = bi[j];
        for (int i=0;i<CFF;i++) acc += sc[i]*W[(size_t)i*DD + j];
        y[jj]=acc;
    }
    float s=(y[0]+y[1])+(y[2]+y[3]);
    red[t]=s; __syncthreads();
    for (int st=128;st>0;st>>=1){ if(t<st) red[t]+=red[t+st]; __syncthreads(); }
    float mu = red[0]*(1.0f/DD);
    __syncthreads();
    float vv=0.f;
#pragma unroll
    for (int jj=0;jj<4;jj++){ float d0=y[jj]-mu; vv += d0*d0; }
    red[t]=vv; __syncthreads();
    for (int st=128;st>0;st>>=1){ if(t<st) red[t]+=red[t+st]; __syncthreads(); }
    float rs = 1.0f/sqrtf(red[0]*(1.0f/DD) + 1e-5f);
#pragma unroll
    for (int jj=0;jj<4;jj++){
        int j = jj*256 + t;
        cadd[(size_t)(p*BB + b)*DD + j] = (y[jj]-mu)*rs*g[j] + be[j];
    }
}

// ---------------- LN + broadcast add ----------------------------------------------
__global__ void lnadd_kernel(float* __restrict__ buf,
    const float* __restrict__ g, const float* __restrict__ be,
    const float* __restrict__ cadd)
{
    __shared__ float red[256];
    int t = threadIdx.x, r = blockIdx.x;
    float4* row = (float4*)(buf + (size_t)r*DD);
    float4 v = row[t];
    red[t]=(v.x+v.y)+(v.z+v.w); __syncthreads();
    for (int st=128;st>0;st>>=1){ if(t<st) red[t]+=red[t+st]; __syncthreads(); }
    float mu = red[0]*(1.0f/DD);
    __syncthreads();
    float dx=v.x-mu, dy=v.y-mu, dz=v.z-mu, dw=v.w-mu;
    red[t]=(dx*dx+dy*dy)+(dz*dz+dw*dw); __syncthreads();
    for (int st=128;st>0;st>>=1){ if(t<st) red[t]+=red[t+st]; __syncthreads(); }
    float rs = 1.0f/sqrtf(red[0]*(1.0f/DD) + 1e-5f);
    float4 gg=((const float4*)g)[t], bb=((const float4*)be)[t];
    float4 cc=((const float4*)(cadd+(size_t)(r>>10)*DD))[t];
    float4 o = {dx*rs*gg.x+bb.x+cc.x, dy*rs*gg.y+bb.y+cc.y,
                dz*rs*gg.z+bb.z+cc.z, dw*rs*gg.w+bb.w+cc.w};
    row[t]=o;
}

// ------------------------------- launch ---------------------------------------------
extern "C" void kernel_launch(void* const* d_in, const int* in_sizes, int n_in,
                              void* d_out, int out_size)
{
    const float* Q    = (const float*)d_in[0];
    const float* c    = (const float*)d_in[1];
    const float* Wq   = (const float*)d_in[2];
    const float* bq   = (const float*)d_in[3];
    const float* Wk   = (const float*)d_in[4];
    const float* bk   = (const float*)d_in[5];
    const float* Wv   = (const float*)d_in[6];
    const float* bv   = (const float*)d_in[7];
    const float* Wcq  = (const float*)d_in[8];
    const float* bcq  = (const float*)d_in[9];
    const float* Wck  = (const float*)d_in[10];
    const float* bck  = (const float*)d_in[11];
    const float* Wcv  = (const float*)d_in[12];
    const float* bcv  = (const float*)d_in[13];
    const float* g_q  = (const float*)d_in[14];
    const float* be_q = (const float*)d_in[15];
    const float* g_qc = (const float*)d_in[16];
    const float* be_qc= (const float*)d_in[17];
    const float* g_k  = (const float*)d_in[18];
    const float* be_k = (const float*)d_in[19];
    const float* g_kc = (const float*)d_in[20];
    const float* be_kc= (const float*)d_in[21];
    const float* g_v  = (const float*)d_in[22];
    const float* be_v = (const float*)d_in[23];
    const float* g_vc = (const float*)d_in[24];
    const float* be_vc= (const float*)d_in[25];
    const float* Wo   = (const float*)d_in[26];
    const float* bo   = (const float*)d_in[27];

    float* out  = (float*)d_out;
    float* attn = out + OUT_ELEMS;

    float *qb,*kb,*vbuf,*cx,*cadd;
    __nv_bfloat16 *apl,*kpl,*wpl,*ppl,*vtp;
    cudaGetSymbolAddress((void**)&qb,   d_qbuf);
    cudaGetSymbolAddress((void**)&kb,   d_kbuf);
    cudaGetSymbolAddress((void**)&vbuf, d_vbuf);
    cudaGetSymbolAddress((void**)&cx,   d_ctxbuf);
    cudaGetSymbolAddress((void**)&cadd, d_caddbuf);
    cudaGetSymbolAddress((void**)&apl,  d_aplanes);
    cudaGetSymbolAddress((void**)&kpl,  d_kplanes);
    cudaGetSymbolAddress((void**)&wpl,  d_wplanes);
    cudaGetSymbolAddress((void**)&ppl,  d_pplanes);
    cudaGetSymbolAddress((void**)&vtp,  d_vtpl);

    cudaFuncSetAttribute(gemm_mma, cudaFuncAttributeMaxDynamicSharedMemorySize, GEMM_SMEM_MAX);
    cudaFuncSetAttribute(qk_mma,   cudaFuncAttributeMaxDynamicSharedMemorySize, 6*QKPL);
    cudaFuncSetAttribute(av_mma,   cudaFuncAttributeMaxDynamicSharedMemorySize, 2*AVA+2*AVB);

    cproj_kernel<<<dim3(3,BB),256>>>(c, Wcq,bcq, Wck,bck, Wcv,bcv,
                                     g_qc,be_qc, g_kc,be_kc, g_vc,be_vc, cadd);

    splitWT_kernel<<<dim3(32,32),256>>>(Wq, wpl + 0*3*WPL);
    splitWT_kernel<<<dim3(32,32),256>>>(Wk, wpl + 1*3*WPL);
    splitWT_kernel<<<dim3(32,32),256>>>(Wv, wpl + 2*3*WPL);
    splitWT_kernel<<<dim3(32,32),256>>>(Wo, wpl + 3*3*WPL);
    splitA_kernel<<<MT,256>>>(Q, apl);

    dim3 gg(DD/128, MT/128);
    gemm_mma<<<gg,256,6*PLSZ>>>(apl, wpl + 0*3*WPL, bq, qb,   6);
    gemm_mma<<<gg,256,6*PLSZ>>>(apl, wpl + 1*3*WPL, bk, kb,   6);
    gemm_mma<<<gg,256,4*PLSZ>>>(apl, wpl + 2*3*WPL, bv, vbuf, 3);

    lnadd_kernel<<<MT,256>>>(qb,   g_q, be_q, cadd + 0*BB*DD);
    lnadd_kernel<<<MT,256>>>(kb,   g_k, be_k, cadd + 1*BB*DD);
    lnadd_kernel<<<MT,256>>>(vbuf, g_v, be_v, cadd + 2*BB*DD);

    // split q,k into 3-term planes; transpose+split V
    splitA_kernel<<<MT,256>>>(qb, apl);
    splitA_kernel<<<MT,256>>>(kb, kpl);
    vtrans_kernel<<<dim3(2,32,BB*HH),256>>>(vbuf, vtp);

    qk_mma<<<dim3(SS/128, SS/128, BB*HH),256,6*QKPL>>>(apl, kpl, attn);
    softmax_kernel<<<BB*HH*SS,256>>>(attn, ppl);
    av_mma<<<dim3(SS/128, BB*HH),256,2*AVA+2*AVB>>>(ppl, vtp, cx);

    splitA_kernel<<<MT,256>>>(cx, apl);
    gemm_mma<<<gg,256,4*PLSZ>>>(apl, wpl + 3*3*WPL, bo, out, 3);
}